// round 7
// baseline (speedup 1.0000x reference)
#include <cuda_runtime.h>
#include <math.h>
#include <stdint.h>

#define BSZ 8
#define SEQ 8192
#define NC  128      // chunks per sequence
#define CS  64       // chunk size (tokens)
#define SPAD 132     // 132 mod 32 == 4 -> conflict-free A fragment LDS

// ---------------- scratch -----------------------------------------------
__device__ float g_at[BSZ * SEQ * 128];
__device__ float g_bt[BSZ * SEQ * 128];
__device__ float g_stA[2][BSZ][NC][128];
__device__ float g_stB[2][BSZ][NC][128];
// fragment-quad weight images: [seg][kstep(16)][ntpair(8)][lane(32)] float4
// = (b0,b1) for ntile 2*ntp and (b0,b1) for ntile 2*ntp+1
// segs: 0 Win, 1 Wi, 2 Wr, 3 WoutF, 4 WoutB, 5-8 W1 chunks, 9-12 W2 chunks
__device__ float4 g_wimg[13][4096];

__device__ __forceinline__ float sigmoidf_(float v) {
    return 1.f / (1.f + expf(-v));
}
__device__ __forceinline__ float geluf_(float v) {
    float u = v + 0.044715f * v * v * v;
    return 0.5f * v * (1.f + tanhf(0.7978845608028654f * u));
}
__device__ __forceinline__ float cvt_tf32(float x) {
    uint32_t u;
    asm("cvt.rna.tf32.f32 %0, %1;" : "=r"(u) : "f"(x));
    return __uint_as_float(u);
}
__device__ __forceinline__ void mma_tf32(float c[4],
    uint32_t a0, uint32_t a1, uint32_t a2, uint32_t a3,
    uint32_t b0, uint32_t b1)
{
    asm("mma.sync.aligned.m16n8k8.row.col.f32.tf32.tf32.f32 "
        "{%0,%1,%2,%3},{%4,%5,%6,%7},{%8,%9},{%0,%1,%2,%3};"
        : "+f"(c[0]), "+f"(c[1]), "+f"(c[2]), "+f"(c[3])
        : "r"(a0), "r"(a1), "r"(a2), "r"(a3), "r"(b0), "r"(b1));
}

// dot(c[128], w[128]) by 32 threads (tid<32); full value in lane 0.
__device__ __forceinline__ float dot32(const float* cvec, const float* w, int tid)
{
    float4 cv = reinterpret_cast<const float4*>(cvec)[tid];
    float4 wv = reinterpret_cast<const float4*>(w)[tid];
    float p = cv.x * wv.x + cv.y * wv.y + cv.z * wv.z + cv.w * wv.w;
    p += __shfl_xor_sync(0xffffffffu, p, 16);
    p += __shfl_xor_sync(0xffffffffu, p, 8);
    p += __shfl_xor_sync(0xffffffffu, p, 4);
    p += __shfl_xor_sync(0xffffffffu, p, 2);
    p += __shfl_xor_sync(0xffffffffu, p, 1);
    return p;
}

// warp computes 16(row) x 64(col) tile of A[..x128] @ W[128x..]; A in smem
// (stride SPAD), B fragment quads loaded straight from the gmem image.
__device__ __forceinline__ void gemm_16x64_g(const float* __restrict__ As,
    const float4* __restrict__ Bimg, int row0, int wn, int lane, int g, int t,
    float c[8][4])
{
#pragma unroll 4
    for (int ks = 0; ks < 16; ks++) {
        const float* Ar = As + (row0 + g) * SPAD + ks * 8 + t;
        uint32_t a0 = __float_as_uint(Ar[0]);
        uint32_t a2 = __float_as_uint(Ar[4]);
        uint32_t a1 = __float_as_uint(Ar[8 * SPAD]);
        uint32_t a3 = __float_as_uint(Ar[8 * SPAD + 4]);
        const float4* Bw = Bimg + ((ks * 8 + wn * 4) << 5) + lane;
#pragma unroll
        for (int jp = 0; jp < 4; jp++) {
            float4 bv = __ldg(Bw + (jp << 5));
            mma_tf32(c[2 * jp],     a0, a1, a2, a3,
                     __float_as_uint(bv.x), __float_as_uint(bv.y));
            mma_tf32(c[2 * jp + 1], a0, a1, a2, a3,
                     __float_as_uint(bv.z), __float_as_uint(bv.w));
        }
    }
}

// ---------------- KP: pack all weights into fragment-quad images ---------
__global__ __launch_bounds__(256) void kp_pack(
    const float* __restrict__ Win, const float* __restrict__ Wi,
    const float* __restrict__ Wr,  const float* __restrict__ Wout,
    const float* __restrict__ W1,  const float* __restrict__ W2)
{
    int seg = blockIdx.x;
    const float* src;
    int ns;
    if (seg == 0)      { src = Win;  ns = 128; }
    else if (seg == 1) { src = Wi;   ns = 128; }
    else if (seg == 2) { src = Wr;   ns = 128; }
    else if (seg == 3) { src = Wout; ns = 128; }
    else if (seg == 4) { src = Wout + 128 * 128; ns = 128; }
    else if (seg < 9)  { src = W1 + (seg - 5) * 128; ns = 512; }
    else               { src = W2 + (seg - 9) * 128 * 128; ns = 128; }
    float4* dst = g_wimg[seg];
    for (int p = threadIdx.x; p < 4096; p += 256) {
        int lane = p & 31, ntp = (p >> 5) & 7, ks = p >> 8;
        int g = lane >> 2, t = lane & 3;
        int k = ks * 8 + t, n = ntp * 16 + g;
        dst[p] = make_float4(cvt_tf32(src[k * ns + n]),
                             cvt_tf32(src[(k + 4) * ns + n]),
                             cvt_tf32(src[k * ns + n + 8]),
                             cvt_tf32(src[(k + 4) * ns + n + 8]));
    }
}

// ---------------- K1: LN -> LN -> (u, gates) -> a_t,b_t ------------------
__global__ __launch_bounds__(256) void k1_pre(
    const float* __restrict__ x,   const float* __restrict__ cvec,
    const float* __restrict__ sw1, const float* __restrict__ sb1,
    const float* __restrict__ bw1, const float* __restrict__ bb1,
    const float* __restrict__ bin, const float* __restrict__ pos,
    const float* __restrict__ bi,  const float* __restrict__ br,
    const float* __restrict__ avec)
{
    extern __shared__ float sm[];
    float* As  = sm;                  // 64*SPAD
    float* L2A = sm + 64 * SPAD;      // 128
    float* sS  = L2A + 128;           // 2
    int tid = threadIdx.x;
    int to  = blockIdx.x * 64;
    int b   = to >> 13;
    int tib = to & (SEQ - 1);

    if (tid < 32) {
        float p0 = dot32(cvec + b * 128, sw1, tid);
        float p1 = dot32(cvec + b * 128, bw1, tid);
        if (tid == 0) { sS[0] = p0 + sb1[0]; sS[1] = p1 + bb1[0]; }
    }
    if (tid >= 128) L2A[tid - 128] = log2f(avec[tid - 128]);
    __syncthreads();
    float alpha = 1.f + sS[0];
    float b1s   = sS[1];

    // ---- LN x2 : 4 threads per token, 32 channels each
    {
        int tt = tid >> 2, q = tid & 3;
        const float4* xp = reinterpret_cast<const float4*>(x + (to + tt) * 128 + q * 32);
        float4 v[8];
#pragma unroll
        for (int i = 0; i < 8; i++) v[i] = xp[i];
        float s = 0.f, ss = 0.f;
#pragma unroll
        for (int i = 0; i < 8; i++) {
            s  += v[i].x + v[i].y + v[i].z + v[i].w;
            ss += v[i].x * v[i].x + v[i].y * v[i].y + v[i].z * v[i].z + v[i].w * v[i].w;
        }
        s  += __shfl_xor_sync(0xffffffffu, s, 1);
        s  += __shfl_xor_sync(0xffffffffu, s, 2);
        ss += __shfl_xor_sync(0xffffffffu, ss, 1);
        ss += __shfl_xor_sync(0xffffffffu, ss, 2);
        float m = s * (1.f / 128.f);
        float rs = rsqrtf(ss * (1.f / 128.f) - m * m + 1e-6f);
        float s2 = 0.f, ss2 = 0.f;
#pragma unroll
        for (int i = 0; i < 8; i++) {
            v[i].x = fmaf(alpha, (v[i].x - m) * rs, b1s);
            v[i].y = fmaf(alpha, (v[i].y - m) * rs, b1s);
            v[i].z = fmaf(alpha, (v[i].z - m) * rs, b1s);
            v[i].w = fmaf(alpha, (v[i].w - m) * rs, b1s);
            s2  += v[i].x + v[i].y + v[i].z + v[i].w;
            ss2 += v[i].x * v[i].x + v[i].y * v[i].y + v[i].z * v[i].z + v[i].w * v[i].w;
        }
        s2  += __shfl_xor_sync(0xffffffffu, s2, 1);
        s2  += __shfl_xor_sync(0xffffffffu, s2, 2);
        ss2 += __shfl_xor_sync(0xffffffffu, ss2, 1);
        ss2 += __shfl_xor_sync(0xffffffffu, ss2, 2);
        float m2 = s2 * (1.f / 128.f);
        float rs2 = rsqrtf(ss2 * (1.f / 128.f) - m2 * m2 + 1e-6f);
        float* Ap = &As[tt * SPAD + q * 32];
#pragma unroll
        for (int i = 0; i < 8; i++) {
            float4 o;
            o.x = cvt_tf32((v[i].x - m2) * rs2);
            o.y = cvt_tf32((v[i].y - m2) * rs2);
            o.z = cvt_tf32((v[i].z - m2) * rs2);
            o.w = cvt_tf32((v[i].w - m2) * rs2);
            *reinterpret_cast<float4*>(Ap + i * 4) = o;
        }
    }
    __syncthreads();

    int lane = tid & 31, wid = tid >> 5;
    int g = lane >> 2, t = lane & 3;
    int wm = wid >> 1, wn = wid & 1;
    int row0 = wm * 16, col0 = wn * 64;

    // GEMM1: u = ln2h @ Win
    float c1[8][4];
#pragma unroll
    for (int j = 0; j < 8; j++)
#pragma unroll
        for (int e = 0; e < 4; e++) c1[j][e] = 0.f;
    gemm_16x64_g(As, g_wimg[0], row0, wn, lane, g, t, c1);
    __syncthreads();

    // u = c1 + bin + pos -> back into As (tf32)
#pragma unroll
    for (int j = 0; j < 8; j++) {
        int n = col0 + 8 * j + 2 * t;
        int r0 = row0 + g, r1 = r0 + 8;
        float2 bb = *reinterpret_cast<const float2*>(bin + n);
        float2 p0 = *reinterpret_cast<const float2*>(pos + (tib + r0) * 128 + n);
        float2 p1 = *reinterpret_cast<const float2*>(pos + (tib + r1) * 128 + n);
        As[r0 * SPAD + n]     = cvt_tf32(c1[j][0] + bb.x + p0.x);
        As[r0 * SPAD + n + 1] = cvt_tf32(c1[j][1] + bb.y + p0.y);
        As[r1 * SPAD + n]     = cvt_tf32(c1[j][2] + bb.x + p1.x);
        As[r1 * SPAD + n + 1] = cvt_tf32(c1[j][3] + bb.y + p1.y);
    }
    __syncthreads();

    // GEMM2: input gate
    float gi[8][4];
#pragma unroll
    for (int j = 0; j < 8; j++)
#pragma unroll
        for (int e = 0; e < 4; e++) gi[j][e] = 0.f;
    gemm_16x64_g(As, g_wimg[1], row0, wn, lane, g, t, gi);
#pragma unroll
    for (int j = 0; j < 8; j++) {
        int n = col0 + 8 * j + 2 * t;
        float2 bb = *reinterpret_cast<const float2*>(bi + n);
        gi[j][0] = sigmoidf_(gi[j][0] + bb.x);
        gi[j][1] = sigmoidf_(gi[j][1] + bb.y);
        gi[j][2] = sigmoidf_(gi[j][2] + bb.x);
        gi[j][3] = sigmoidf_(gi[j][3] + bb.y);
    }

    // GEMM3: recurrence gate (As unchanged, no sync needed)
#pragma unroll
    for (int j = 0; j < 8; j++)
#pragma unroll
        for (int e = 0; e < 4; e++) c1[j][e] = 0.f;
    gemm_16x64_g(As, g_wimg[2], row0, wn, lane, g, t, c1);

    // epilogue: a_t, b_t
#pragma unroll
    for (int j = 0; j < 8; j++) {
        int n = col0 + 8 * j + 2 * t;
        int r0 = row0 + g, r1 = r0 + 8;
        float2 bb = *reinterpret_cast<const float2*>(br + n);
        float la0 = L2A[n], la1 = L2A[n + 1];
        float u00 = As[r0 * SPAD + n], u01 = As[r0 * SPAD + n + 1];
        float u10 = As[r1 * SPAD + n], u11 = As[r1 * SPAD + n + 1];
        float at00 = exp2f(8.f * sigmoidf_(c1[j][0] + bb.x) * la0);
        float at01 = exp2f(8.f * sigmoidf_(c1[j][1] + bb.y) * la1);
        float at10 = exp2f(8.f * sigmoidf_(c1[j][2] + bb.x) * la0);
        float at11 = exp2f(8.f * sigmoidf_(c1[j][3] + bb.y) * la1);
        float bt00 = sqrtf(fmaxf(1.f - at00 * at00, 0.f)) * gi[j][0] * u00;
        float bt01 = sqrtf(fmaxf(1.f - at01 * at01, 0.f)) * gi[j][1] * u01;
        float bt10 = sqrtf(fmaxf(1.f - at10 * at10, 0.f)) * gi[j][2] * u10;
        float bt11 = sqrtf(fmaxf(1.f - at11 * at11, 0.f)) * gi[j][3] * u11;
        int i0 = (to + r0) * 128 + n;
        int i1 = (to + r1) * 128 + n;
        *reinterpret_cast<float2*>(g_at + i0) = make_float2(at00, at01);
        *reinterpret_cast<float2*>(g_at + i1) = make_float2(at10, at11);
        *reinterpret_cast<float2*>(g_bt + i0) = make_float2(bt00, bt01);
        *reinterpret_cast<float2*>(g_bt + i1) = make_float2(bt10, bt11);
    }
}

// ---------------- K2a: per-chunk scan states (CS=64) ---------------------
__global__ __launch_bounds__(256) void k2a_chunk()
{
    int blk = blockIdx.x;
    int b = blk >> 7, ci = blk & 127;
    int tid = threadIdx.x;
    int dir = tid >> 7, h = tid & 127;
    int base = ((b << 13) + (ci << 6)) * 128 + h;
    float Ap = 1.f, Bv = 0.f;
    if (dir == 0) {
#pragma unroll 4
        for (int s = 0; s < CS; s++) {
            int idx = base + (s << 7);
            float a = g_at[idx], bb = g_bt[idx];
            Ap *= a;
            Bv = fmaf(a, Bv, bb);
        }
    } else {
#pragma unroll 4
        for (int s = CS - 1; s >= 0; s--) {
            int idx = base + (s << 7);
            float a = g_at[idx], bb = g_bt[idx];
            Ap *= a;
            Bv = fmaf(a, Bv, bb);
        }
    }
    g_stA[dir][b][ci][h] = Ap;
    g_stB[dir][b][ci][h] = Bv;
}

// ---------------- K3: prefix + re-scan + out-GEMM + residual -------------
__global__ __launch_bounds__(256) void k3_scan_out(
    const float* __restrict__ x, const float* __restrict__ cvec,
    const float* __restrict__ g1w, const float* __restrict__ g1b,
    const float* __restrict__ bout, float* __restrict__ out)
{
    extern __shared__ float sm[];
    float* HF = sm;                 // 64*SPAD
    float* HB = sm + 64 * SPAD;     // 64*SPAD
    float* sG = sm + 128 * SPAD;    // 1
    int blk = blockIdx.x;
    int b = blk >> 7, ci = blk & 127;
    int tid = threadIdx.x;

    if (tid < 32) {
        float p = dot32(cvec + b * 128, g1w, tid);
        if (tid == 0) sG[0] = p + g1b[0];
    }
    {
        int dir = tid >> 7, h = tid & 127;
        // batched prefix fold over predecessor chunk states
        float hc = 0.f;
        if (dir == 0) {
            int j = 0;
            while (j < ci) {
                int nb = ci - j; if (nb > 16) nb = 16;
                float av[16], bv[16];
#pragma unroll
                for (int q = 0; q < 16; q++)
                    if (q < nb) {
                        av[q] = g_stA[0][b][j + q][h];
                        bv[q] = g_stB[0][b][j + q][h];
                    }
#pragma unroll
                for (int q = 0; q < 16; q++)
                    if (q < nb) hc = fmaf(av[q], hc, bv[q]);
                j += nb;
            }
        } else {
            int j = NC - 1;
            while (j > ci) {
                int nb = j - ci; if (nb > 16) nb = 16;
                float av[16], bv[16];
#pragma unroll
                for (int q = 0; q < 16; q++)
                    if (q < nb) {
                        av[q] = g_stA[1][b][j - q][h];
                        bv[q] = g_stB[1][b][j - q][h];
                    }
#pragma unroll
                for (int q = 0; q < 16; q++)
                    if (q < nb) hc = fmaf(av[q], hc, bv[q]);
                j -= nb;
            }
        }
        int base = ((b << 13) + (ci << 6)) * 128 + h;
        if (dir == 0) {
#pragma unroll 4
            for (int s = 0; s < CS; s++) {
                int idx = base + (s << 7);
                hc = fmaf(g_at[idx], hc, g_bt[idx]);
                HF[s * SPAD + h] = cvt_tf32(hc);
            }
        } else {
#pragma unroll 4
            for (int s = CS - 1; s >= 0; s--) {
                int idx = base + (s << 7);
                hc = fmaf(g_at[idx], hc, g_bt[idx]);
                HB[s * SPAD + h] = cvt_tf32(hc);
            }
        }
    }
    __syncthreads();

    int lane = tid & 31, wid = tid >> 5;
    int g = lane >> 2, t = lane & 3;
    int wm = wid >> 1, wn = wid & 1;
    int row0 = wm * 16, col0 = wn * 64;
    float c[8][4];
#pragma unroll
    for (int j = 0; j < 8; j++)
#pragma unroll
        for (int e = 0; e < 4; e++) c[j][e] = 0.f;
    gemm_16x64_g(HF, g_wimg[3], row0, wn, lane, g, t, c);
    gemm_16x64_g(HB, g_wimg[4], row0, wn, lane, g, t, c);

    float g1 = sG[0];
    int tbase = (b << 13) + (ci << 6);
#pragma unroll
    for (int j = 0; j < 8; j++) {
        int n = col0 + 8 * j + 2 * t;
        int r0 = row0 + g, r1 = r0 + 8;
        float2 bb = *reinterpret_cast<const float2*>(bout + n);
        int i0 = (tbase + r0) * 128 + n;
        int i1 = (tbase + r1) * 128 + n;
        float2 x0 = *reinterpret_cast<const float2*>(x + i0);
        float2 x1 = *reinterpret_cast<const float2*>(x + i1);
        float2 o0, o1;
        o0.x = fmaf(g1, c[j][0] + bb.x, x0.x);
        o0.y = fmaf(g1, c[j][1] + bb.y, x0.y);
        o1.x = fmaf(g1, c[j][2] + bb.x, x1.x);
        o1.y = fmaf(g1, c[j][3] + bb.y, x1.y);
        *reinterpret_cast<float2*>(out + i0) = o0;
        *reinterpret_cast<float2*>(out + i1) = o1;
    }
}

// ---------------- K4: cond-LN -> GELU MLP -> gated residual --------------
__global__ __launch_bounds__(256) void k4_mlp(
    float* __restrict__ out, const float* __restrict__ cvec,
    const float* __restrict__ sw2, const float* __restrict__ sb2,
    const float* __restrict__ bw2, const float* __restrict__ bb2,
    const float* __restrict__ g2w, const float* __restrict__ g2b,
    const float* __restrict__ b1v, const float* __restrict__ b2v)
{
    extern __shared__ float sm[];
    float* HS  = sm;                  // 64*SPAD
    float* M1c = sm + 64 * SPAD;      // 64*SPAD
    float* sS  = sm + 128 * SPAD;     // 3
    int tid = threadIdx.x;
    int to = blockIdx.x * 64;
    int b = to >> 13;

    if (tid < 32) {
        float p0 = dot32(cvec + b * 128, sw2, tid);
        float p1 = dot32(cvec + b * 128, bw2, tid);
        float p2 = dot32(cvec + b * 128, g2w, tid);
        if (tid == 0) {
            sS[0] = p0 + sb2[0];
            sS[1] = p1 + bb2[0];
            sS[2] = p2 + g2b[0];
        }
    }
    __syncthreads();
    float alpha = 1.f + sS[0];
    float b2s = sS[1], g2 = sS[2];

    // LN: 4 threads per token, 32 channels each
    {
        int tt = tid >> 2, q = tid & 3;
        const float4* xp = reinterpret_cast<const float4*>(out + (to + tt) * 128 + q * 32);
        float4 v[8];
#pragma unroll
        for (int i = 0; i < 8; i++) v[i] = xp[i];
        float s = 0.f, ss = 0.f;
#pragma unroll
        for (int i = 0; i < 8; i++) {
            s  += v[i].x + v[i].y + v[i].z + v[i].w;
            ss += v[i].x * v[i].x + v[i].y * v[i].y + v[i].z * v[i].z + v[i].w * v[i].w;
        }
        s  += __shfl_xor_sync(0xffffffffu, s, 1);
        s  += __shfl_xor_sync(0xffffffffu, s, 2);
        ss += __shfl_xor_sync(0xffffffffu, ss, 1);
        ss += __shfl_xor_sync(0xffffffffu, ss, 2);
        float m = s * (1.f / 128.f);
        float rs = rsqrtf(ss * (1.f / 128.f) - m * m + 1e-6f);
        float* hp = &HS[tt * SPAD + q * 32];
#pragma unroll
        for (int i = 0; i < 8; i++) {
            float4 o;
            o.x = cvt_tf32(fmaf(alpha, (v[i].x - m) * rs, b2s));
            o.y = cvt_tf32(fmaf(alpha, (v[i].y - m) * rs, b2s));
            o.z = cvt_tf32(fmaf(alpha, (v[i].z - m) * rs, b2s));
            o.w = cvt_tf32(fmaf(alpha, (v[i].w - m) * rs, b2s));
            *reinterpret_cast<float4*>(hp + i * 4) = o;
        }
    }
    __syncthreads();

    int lane = tid & 31, wid = tid >> 5;
    int g = lane >> 2, t = lane & 3;
    int wm = wid >> 1, wn = wid & 1;
    int row0 = wm * 16, col0 = wn * 64;

    float C2[8][4];
#pragma unroll
    for (int j = 0; j < 8; j++)
#pragma unroll
        for (int e = 0; e < 4; e++) C2[j][e] = 0.f;

    for (int ch = 0; ch < 4; ch++) {
        float c1[8][4];
#pragma unroll
        for (int j = 0; j < 8; j++)
#pragma unroll
            for (int e = 0; e < 4; e++) c1[j][e] = 0.f;
        gemm_16x64_g(HS, g_wimg[5 + ch], row0, wn, lane, g, t, c1);

        __syncthreads();   // prev-chunk gemm2 readers of M1c done
        // gelu -> M1c (tf32)
#pragma unroll
        for (int j = 0; j < 8; j++) {
            int n = col0 + 8 * j + 2 * t;
            int r0 = row0 + g, r1 = r0 + 8;
            float2 bb = *reinterpret_cast<const float2*>(b1v + ch * 128 + n);
            M1c[r0 * SPAD + n]     = cvt_tf32(geluf_(c1[j][0] + bb.x));
            M1c[r0 * SPAD + n + 1] = cvt_tf32(geluf_(c1[j][1] + bb.y));
            M1c[r1 * SPAD + n]     = cvt_tf32(geluf_(c1[j][2] + bb.x));
            M1c[r1 * SPAD + n + 1] = cvt_tf32(geluf_(c1[j][3] + bb.y));
        }
        __syncthreads();
        gemm_16x64_g(M1c, g_wimg[9 + ch], row0, wn, lane, g, t, C2);
    }

    // epilogue (in-place gated residual)
#pragma unroll
    for (int j = 0; j < 8; j++) {
        int n = col0 + 8 * j + 2 * t;
        int r0 = row0 + g, r1 = r0 + 8;
        float2 bb = *reinterpret_cast<const float2*>(b2v + n);
        int i0 = (to + r0) * 128 + n;
        int i1 = (to + r1) * 128 + n;
        float2 x0 = *reinterpret_cast<const float2*>(out + i0);
        float2 x1 = *reinterpret_cast<const float2*>(out + i1);
        float2 o0, o1;
        o0.x = fmaf(g2, C2[j][0] + bb.x, x0.x);
        o0.y = fmaf(g2, C2[j][1] + bb.y, x0.y);
        o1.x = fmaf(g2, C2[j][2] + bb.x, x1.x);
        o1.y = fmaf(g2, C2[j][3] + bb.y, x1.y);
        *reinterpret_cast<float2*>(out + i0) = o0;
        *reinterpret_cast<float2*>(out + i1) = o1;
    }
}

// ---------------- launch -------------------------------------------------
extern "C" void kernel_launch(void* const* d_in, const int* in_sizes, int n_in,
                              void* d_out, int out_size)
{
    const float* x        = (const float*)d_in[0];
    const float* c        = (const float*)d_in[1];
    const float* cln1_sw  = (const float*)d_in[2];
    const float* cln1_sb  = (const float*)d_in[3];
    const float* cln1_bw  = (const float*)d_in[4];
    const float* cln1_bb  = (const float*)d_in[5];
    const float* gate1_w  = (const float*)d_in[6];
    const float* gate1_b  = (const float*)d_in[7];
    const float* rnn_in_w = (const float*)d_in[8];
    const float* rnn_in_b = (const float*)d_in[9];
    const float* pos_emb  = (const float*)d_in[10];
    const float* rnn_wi   = (const float*)d_in[11];
    const float* rnn_bi   = (const float*)d_in[12];
    const float* rnn_wr   = (const float*)d_in[13];
    const float* rnn_br   = (const float*)d_in[14];
    const float* rnn_a    = (const float*)d_in[15];
    const float* rnn_out_w= (const float*)d_in[16];
    const float* rnn_out_b= (const float*)d_in[17];
    const float* cln2_sw  = (const float*)d_in[18];
    const float* cln2_sb  = (const float*)d_in[19];
    const float* cln2_bw  = (const float*)d_in[20];
    const float* cln2_bb  = (const float*)d_in[21];
    const float* gate2_w  = (const float*)d_in[22];
    const float* gate2_b  = (const float*)d_in[23];
    const float* mlp_w1   = (const float*)d_in[24];
    const float* mlp_b1   = (const float*)d_in[25];
    const float* mlp_w2   = (const float*)d_in[26];
    const float* mlp_b2   = (const float*)d_in[27];
    float* out = (float*)d_out;

    const int SM1 = (64 * SPAD + 128 + 2) * 4;        // ~34 KB
    const int SM3 = (128 * SPAD + 4) * 4;             // ~67.6 KB -> 3 CTAs/SM
    const int SM4 = (128 * SPAD + 4) * 4;             // ~67.6 KB -> 3 CTAs/SM
    cudaFuncSetAttribute(k3_scan_out, cudaFuncAttributeMaxDynamicSharedMemorySize, SM3);
    cudaFuncSetAttribute(k4_mlp,      cudaFuncAttributeMaxDynamicSharedMemorySize, SM4);

    kp_pack<<<13, 256>>>(rnn_in_w, rnn_wi, rnn_wr, rnn_out_w, mlp_w1, mlp_w2);
    k1_pre<<<1024, 256, SM1>>>(x, c, cln1_sw, cln1_sb, cln1_bw, cln1_bb,
                               rnn_in_b, pos_emb, rnn_bi, rnn_br, rnn_a);
    k2a_chunk<<<1024, 256>>>();
    k3_scan_out<<<1024, 256, SM3>>>(x, c, gate1_w, gate1_b, rnn_out_b, out);
    k4_mlp<<<1024, 256, SM4>>>(out, c, cln2_sw, cln2_sb, cln2_bw, cln2_bb,
                               gate2_w, gate2_b, mlp_b1, mlp_b2);
}

// round 8
// speedup vs baseline: 1.0084x; 1.0084x over previous
#include <cuda_runtime.h>
#include <math.h>
#include <stdint.h>

#define BSZ 8
#define SEQ 8192
#define NC  128      // chunks per sequence
#define CS  64       // chunk size == k1 tile size
#define SPAD 132     // 132 mod 32 == 4 -> conflict-free A fragment LDS

// ---------------- scratch -----------------------------------------------
__device__ float g_at[BSZ * SEQ * 128];
__device__ float g_bt[BSZ * SEQ * 128];
__device__ float g_stA[2][BSZ][NC][128];
__device__ float g_stB[2][BSZ][NC][128];
// fragment-quad weight images: [seg][kstep(16)][ntpair(8)][lane(32)] float4
// segs: 0 Win, 1 Wi, 2 Wr, 3 WoutF, 4 WoutB, 5-8 W1 chunks, 9-12 W2 chunks
__device__ float4 g_wimg[13][4096];

__device__ __forceinline__ float sigmoidf_(float v) {
    return 1.f / (1.f + expf(-v));
}
__device__ __forceinline__ float geluf_(float v) {
    float u = v + 0.044715f * v * v * v;
    return 0.5f * v * (1.f + tanhf(0.7978845608028654f * u));
}
__device__ __forceinline__ float cvt_tf32(float x) {
    uint32_t u;
    asm("cvt.rna.tf32.f32 %0, %1;" : "=r"(u) : "f"(x));
    return __uint_as_float(u);
}
__device__ __forceinline__ void mma_tf32(float c[4],
    uint32_t a0, uint32_t a1, uint32_t a2, uint32_t a3,
    uint32_t b0, uint32_t b1)
{
    asm("mma.sync.aligned.m16n8k8.row.col.f32.tf32.tf32.f32 "
        "{%0,%1,%2,%3},{%4,%5,%6,%7},{%8,%9},{%0,%1,%2,%3};"
        : "+f"(c[0]), "+f"(c[1]), "+f"(c[2]), "+f"(c[3])
        : "r"(a0), "r"(a1), "r"(a2), "r"(a3), "r"(b0), "r"(b1));
}

// dot(c[128], w[128]) by 32 threads (tid<32); full value in lane 0.
__device__ __forceinline__ float dot32(const float* cvec, const float* w, int tid)
{
    float4 cv = reinterpret_cast<const float4*>(cvec)[tid];
    float4 wv = reinterpret_cast<const float4*>(w)[tid];
    float p = cv.x * wv.x + cv.y * wv.y + cv.z * wv.z + cv.w * wv.w;
    p += __shfl_xor_sync(0xffffffffu, p, 16);
    p += __shfl_xor_sync(0xffffffffu, p, 8);
    p += __shfl_xor_sync(0xffffffffu, p, 4);
    p += __shfl_xor_sync(0xffffffffu, p, 2);
    p += __shfl_xor_sync(0xffffffffu, p, 1);
    return p;
}

// warp computes 16(row) x 64(col) tile of A[..x128] @ W[128x..]; A in smem
// (stride SPAD), B fragment quads loaded straight from the gmem image.
__device__ __forceinline__ void gemm_16x64_g(const float* __restrict__ As,
    const float4* __restrict__ Bimg, int row0, int wn, int lane, int g, int t,
    float c[8][4])
{
#pragma unroll 4
    for (int ks = 0; ks < 16; ks++) {
        const float* Ar = As + (row0 + g) * SPAD + ks * 8 + t;
        uint32_t a0 = __float_as_uint(Ar[0]);
        uint32_t a2 = __float_as_uint(Ar[4]);
        uint32_t a1 = __float_as_uint(Ar[8 * SPAD]);
        uint32_t a3 = __float_as_uint(Ar[8 * SPAD + 4]);
        const float4* Bw = Bimg + ((ks * 8 + wn * 4) << 5) + lane;
#pragma unroll
        for (int jp = 0; jp < 4; jp++) {
            float4 bv = __ldg(Bw + (jp << 5));
            mma_tf32(c[2 * jp],     a0, a1, a2, a3,
                     __float_as_uint(bv.x), __float_as_uint(bv.y));
            mma_tf32(c[2 * jp + 1], a0, a1, a2, a3,
                     __float_as_uint(bv.z), __float_as_uint(bv.w));
        }
    }
}

// ---------------- KP: pack all weights into fragment-quad images ---------
__global__ __launch_bounds__(256) void kp_pack(
    const float* __restrict__ Win, const float* __restrict__ Wi,
    const float* __restrict__ Wr,  const float* __restrict__ Wout,
    const float* __restrict__ W1,  const float* __restrict__ W2)
{
    int seg = blockIdx.x;
    const float* src;
    int ns;
    if (seg == 0)      { src = Win;  ns = 128; }
    else if (seg == 1) { src = Wi;   ns = 128; }
    else if (seg == 2) { src = Wr;   ns = 128; }
    else if (seg == 3) { src = Wout; ns = 128; }
    else if (seg == 4) { src = Wout + 128 * 128; ns = 128; }
    else if (seg < 9)  { src = W1 + (seg - 5) * 128; ns = 512; }
    else               { src = W2 + (seg - 9) * 128 * 128; ns = 128; }
    float4* dst = g_wimg[seg];
    for (int p = threadIdx.x; p < 4096; p += 256) {
        int lane = p & 31, ntp = (p >> 5) & 7, ks = p >> 8;
        int g = lane >> 2, t = lane & 3;
        int k = ks * 8 + t, n = ntp * 16 + g;
        dst[p] = make_float4(cvt_tf32(src[k * ns + n]),
                             cvt_tf32(src[(k + 4) * ns + n]),
                             cvt_tf32(src[k * ns + n + 8]),
                             cvt_tf32(src[(k + 4) * ns + n + 8]));
    }
}

// ---------------- K1: LN->LN->(u,gates)->a_t,b_t + chunk states ----------
__global__ __launch_bounds__(256) void k1_pre(
    const float* __restrict__ x,   const float* __restrict__ cvec,
    const float* __restrict__ sw1, const float* __restrict__ sb1,
    const float* __restrict__ bw1, const float* __restrict__ bb1,
    const float* __restrict__ bin, const float* __restrict__ pos,
    const float* __restrict__ bi,  const float* __restrict__ br,
    const float* __restrict__ avec)
{
    extern __shared__ float sm[];
    float* As  = sm;                          // 64*SPAD
    float* ATs = sm + 64 * SPAD;              // 64*SPAD (a_t tile)
    float* BTs = sm + 128 * SPAD;             // 64*SPAD (b_t tile)
    float* L2A = sm + 192 * SPAD;             // 128
    float* sS  = L2A + 128;                   // 2
    int tid = threadIdx.x;
    int blk = blockIdx.x;
    int to  = blk * 64;
    int b   = blk >> 7;
    int ci  = blk & 127;
    int tib = to & (SEQ - 1);

    if (tid < 32) {
        float p0 = dot32(cvec + b * 128, sw1, tid);
        float p1 = dot32(cvec + b * 128, bw1, tid);
        if (tid == 0) { sS[0] = p0 + sb1[0]; sS[1] = p1 + bb1[0]; }
    }
    if (tid >= 128) L2A[tid - 128] = log2f(avec[tid - 128]);
    __syncthreads();
    float alpha = 1.f + sS[0];
    float b1s   = sS[1];

    // ---- LN x2 : 4 threads per token, 32 channels each
    {
        int tt = tid >> 2, q = tid & 3;
        const float4* xp = reinterpret_cast<const float4*>(x + (to + tt) * 128 + q * 32);
        float4 v[8];
#pragma unroll
        for (int i = 0; i < 8; i++) v[i] = xp[i];
        float s = 0.f, ss = 0.f;
#pragma unroll
        for (int i = 0; i < 8; i++) {
            s  += v[i].x + v[i].y + v[i].z + v[i].w;
            ss += v[i].x * v[i].x + v[i].y * v[i].y + v[i].z * v[i].z + v[i].w * v[i].w;
        }
        s  += __shfl_xor_sync(0xffffffffu, s, 1);
        s  += __shfl_xor_sync(0xffffffffu, s, 2);
        ss += __shfl_xor_sync(0xffffffffu, ss, 1);
        ss += __shfl_xor_sync(0xffffffffu, ss, 2);
        float m = s * (1.f / 128.f);
        float rs = rsqrtf(ss * (1.f / 128.f) - m * m + 1e-6f);
        float s2 = 0.f, ss2 = 0.f;
#pragma unroll
        for (int i = 0; i < 8; i++) {
            v[i].x = fmaf(alpha, (v[i].x - m) * rs, b1s);
            v[i].y = fmaf(alpha, (v[i].y - m) * rs, b1s);
            v[i].z = fmaf(alpha, (v[i].z - m) * rs, b1s);
            v[i].w = fmaf(alpha, (v[i].w - m) * rs, b1s);
            s2  += v[i].x + v[i].y + v[i].z + v[i].w;
            ss2 += v[i].x * v[i].x + v[i].y * v[i].y + v[i].z * v[i].z + v[i].w * v[i].w;
        }
        s2  += __shfl_xor_sync(0xffffffffu, s2, 1);
        s2  += __shfl_xor_sync(0xffffffffu, s2, 2);
        ss2 += __shfl_xor_sync(0xffffffffu, ss2, 1);
        ss2 += __shfl_xor_sync(0xffffffffu, ss2, 2);
        float m2 = s2 * (1.f / 128.f);
        float rs2 = rsqrtf(ss2 * (1.f / 128.f) - m2 * m2 + 1e-6f);
        float* Ap = &As[tt * SPAD + q * 32];
#pragma unroll
        for (int i = 0; i < 8; i++) {
            float4 o;
            o.x = cvt_tf32((v[i].x - m2) * rs2);
            o.y = cvt_tf32((v[i].y - m2) * rs2);
            o.z = cvt_tf32((v[i].z - m2) * rs2);
            o.w = cvt_tf32((v[i].w - m2) * rs2);
            *reinterpret_cast<float4*>(Ap + i * 4) = o;
        }
    }
    __syncthreads();

    int lane = tid & 31, wid = tid >> 5;
    int g = lane >> 2, t = lane & 3;
    int wm = wid >> 1, wn = wid & 1;
    int row0 = wm * 16, col0 = wn * 64;

    // GEMM1: u = ln2h @ Win
    float c1[8][4];
#pragma unroll
    for (int j = 0; j < 8; j++)
#pragma unroll
        for (int e = 0; e < 4; e++) c1[j][e] = 0.f;
    gemm_16x64_g(As, g_wimg[0], row0, wn, lane, g, t, c1);
    __syncthreads();

    // u = c1 + bin + pos -> back into As (tf32)
#pragma unroll
    for (int j = 0; j < 8; j++) {
        int n = col0 + 8 * j + 2 * t;
        int r0 = row0 + g, r1 = r0 + 8;
        float2 bb = *reinterpret_cast<const float2*>(bin + n);
        float2 p0 = *reinterpret_cast<const float2*>(pos + (tib + r0) * 128 + n);
        float2 p1 = *reinterpret_cast<const float2*>(pos + (tib + r1) * 128 + n);
        As[r0 * SPAD + n]     = cvt_tf32(c1[j][0] + bb.x + p0.x);
        As[r0 * SPAD + n + 1] = cvt_tf32(c1[j][1] + bb.y + p0.y);
        As[r1 * SPAD + n]     = cvt_tf32(c1[j][2] + bb.x + p1.x);
        As[r1 * SPAD + n + 1] = cvt_tf32(c1[j][3] + bb.y + p1.y);
    }
    __syncthreads();

    // GEMM2: input gate
    float gi[8][4];
#pragma unroll
    for (int j = 0; j < 8; j++)
#pragma unroll
        for (int e = 0; e < 4; e++) gi[j][e] = 0.f;
    gemm_16x64_g(As, g_wimg[1], row0, wn, lane, g, t, gi);
#pragma unroll
    for (int j = 0; j < 8; j++) {
        int n = col0 + 8 * j + 2 * t;
        float2 bb = *reinterpret_cast<const float2*>(bi + n);
        gi[j][0] = sigmoidf_(gi[j][0] + bb.x);
        gi[j][1] = sigmoidf_(gi[j][1] + bb.y);
        gi[j][2] = sigmoidf_(gi[j][2] + bb.x);
        gi[j][3] = sigmoidf_(gi[j][3] + bb.y);
    }

    // GEMM3: recurrence gate (As unchanged, no sync needed)
#pragma unroll
    for (int j = 0; j < 8; j++)
#pragma unroll
        for (int e = 0; e < 4; e++) c1[j][e] = 0.f;
    gemm_16x64_g(As, g_wimg[2], row0, wn, lane, g, t, c1);

    // epilogue: a_t, b_t -> gmem AND smem tiles
#pragma unroll
    for (int j = 0; j < 8; j++) {
        int n = col0 + 8 * j + 2 * t;
        int r0 = row0 + g, r1 = r0 + 8;
        float2 bb = *reinterpret_cast<const float2*>(br + n);
        float la0 = L2A[n], la1 = L2A[n + 1];
        float u00 = As[r0 * SPAD + n], u01 = As[r0 * SPAD + n + 1];
        float u10 = As[r1 * SPAD + n], u11 = As[r1 * SPAD + n + 1];
        float at00 = exp2f(8.f * sigmoidf_(c1[j][0] + bb.x) * la0);
        float at01 = exp2f(8.f * sigmoidf_(c1[j][1] + bb.y) * la1);
        float at10 = exp2f(8.f * sigmoidf_(c1[j][2] + bb.x) * la0);
        float at11 = exp2f(8.f * sigmoidf_(c1[j][3] + bb.y) * la1);
        float bt00 = sqrtf(fmaxf(1.f - at00 * at00, 0.f)) * gi[j][0] * u00;
        float bt01 = sqrtf(fmaxf(1.f - at01 * at01, 0.f)) * gi[j][1] * u01;
        float bt10 = sqrtf(fmaxf(1.f - at10 * at10, 0.f)) * gi[j][2] * u10;
        float bt11 = sqrtf(fmaxf(1.f - at11 * at11, 0.f)) * gi[j][3] * u11;
        int i0 = (to + r0) * 128 + n;
        int i1 = (to + r1) * 128 + n;
        *reinterpret_cast<float2*>(g_at + i0) = make_float2(at00, at01);
        *reinterpret_cast<float2*>(g_at + i1) = make_float2(at10, at11);
        *reinterpret_cast<float2*>(g_bt + i0) = make_float2(bt00, bt01);
        *reinterpret_cast<float2*>(g_bt + i1) = make_float2(bt10, bt11);
        *reinterpret_cast<float2*>(&ATs[r0 * SPAD + n]) = make_float2(at00, at01);
        *reinterpret_cast<float2*>(&ATs[r1 * SPAD + n]) = make_float2(at10, at11);
        *reinterpret_cast<float2*>(&BTs[r0 * SPAD + n]) = make_float2(bt00, bt01);
        *reinterpret_cast<float2*>(&BTs[r1 * SPAD + n]) = make_float2(bt10, bt11);
    }
    __syncthreads();

    // fused chunk-state fold (was k2a): 2 dirs x 128 channels
    {
        int dir = tid >> 7, h = tid & 127;
        float Ap = 1.f, Bv = 0.f;
        if (dir == 0) {
#pragma unroll 8
            for (int s = 0; s < CS; s++) {
                float a = ATs[s * SPAD + h], bb = BTs[s * SPAD + h];
                Ap *= a;
                Bv = fmaf(a, Bv, bb);
            }
        } else {
#pragma unroll 8
            for (int s = CS - 1; s >= 0; s--) {
                float a = ATs[s * SPAD + h], bb = BTs[s * SPAD + h];
                Ap *= a;
                Bv = fmaf(a, Bv, bb);
            }
        }
        g_stA[dir][b][ci][h] = Ap;
        g_stB[dir][b][ci][h] = Bv;
    }
}

// ---------------- K3: prefix + re-scan + out-GEMM + residual -------------
__global__ __launch_bounds__(256) void k3_scan_out(
    const float* __restrict__ x, const float* __restrict__ cvec,
    const float* __restrict__ g1w, const float* __restrict__ g1b,
    const float* __restrict__ bout, float* __restrict__ out)
{
    extern __shared__ float sm[];
    float* HF = sm;                 // 64*SPAD
    float* HB = sm + 64 * SPAD;     // 64*SPAD
    float* sG = sm + 128 * SPAD;    // 1
    int blk = blockIdx.x;
    int b = blk >> 7, ci = blk & 127;
    int tid = threadIdx.x;

    if (tid < 32) {
        float p = dot32(cvec + b * 128, g1w, tid);
        if (tid == 0) sG[0] = p + g1b[0];
    }
    {
        int dir = tid >> 7, h = tid & 127;
        // batched prefix fold over predecessor chunk states
        float hc = 0.f;
        if (dir == 0) {
            int j = 0;
            while (j < ci) {
                int nb = ci - j; if (nb > 16) nb = 16;
                float av[16], bv[16];
#pragma unroll
                for (int q = 0; q < 16; q++)
                    if (q < nb) {
                        av[q] = g_stA[0][b][j + q][h];
                        bv[q] = g_stB[0][b][j + q][h];
                    }
#pragma unroll
                for (int q = 0; q < 16; q++)
                    if (q < nb) hc = fmaf(av[q], hc, bv[q]);
                j += nb;
            }
        } else {
            int j = NC - 1;
            while (j > ci) {
                int nb = j - ci; if (nb > 16) nb = 16;
                float av[16], bv[16];
#pragma unroll
                for (int q = 0; q < 16; q++)
                    if (q < nb) {
                        av[q] = g_stA[1][b][j - q][h];
                        bv[q] = g_stB[1][b][j - q][h];
                    }
#pragma unroll
                for (int q = 0; q < 16; q++)
                    if (q < nb) hc = fmaf(av[q], hc, bv[q]);
                j -= nb;
            }
        }
        // chunk re-scan with batched prefetch (MLP ~16)
        int base = ((b << 13) + (ci << 6)) * 128 + h;
        if (dir == 0) {
            for (int s0 = 0; s0 < CS; s0 += 8) {
                float av[8], bv[8];
#pragma unroll
                for (int q = 0; q < 8; q++) {
                    int idx = base + ((s0 + q) << 7);
                    av[q] = g_at[idx];
                    bv[q] = g_bt[idx];
                }
#pragma unroll
                for (int q = 0; q < 8; q++) {
                    hc = fmaf(av[q], hc, bv[q]);
                    HF[(s0 + q) * SPAD + h] = cvt_tf32(hc);
                }
            }
        } else {
            for (int s0 = CS - 1; s0 >= 0; s0 -= 8) {
                float av[8], bv[8];
#pragma unroll
                for (int q = 0; q < 8; q++) {
                    int idx = base + ((s0 - q) << 7);
                    av[q] = g_at[idx];
                    bv[q] = g_bt[idx];
                }
#pragma unroll
                for (int q = 0; q < 8; q++) {
                    hc = fmaf(av[q], hc, bv[q]);
                    HB[(s0 - q) * SPAD + h] = cvt_tf32(hc);
                }
            }
        }
    }
    __syncthreads();

    int lane = tid & 31, wid = tid >> 5;
    int g = lane >> 2, t = lane & 3;
    int wm = wid >> 1, wn = wid & 1;
    int row0 = wm * 16, col0 = wn * 64;
    float c[8][4];
#pragma unroll
    for (int j = 0; j < 8; j++)
#pragma unroll
        for (int e = 0; e < 4; e++) c[j][e] = 0.f;
    gemm_16x64_g(HF, g_wimg[3], row0, wn, lane, g, t, c);
    gemm_16x64_g(HB, g_wimg[4], row0, wn, lane, g, t, c);

    float g1 = sG[0];
    int tbase = (b << 13) + (ci << 6);
#pragma unroll
    for (int j = 0; j < 8; j++) {
        int n = col0 + 8 * j + 2 * t;
        int r0 = row0 + g, r1 = r0 + 8;
        float2 bb = *reinterpret_cast<const float2*>(bout + n);
        int i0 = (tbase + r0) * 128 + n;
        int i1 = (tbase + r1) * 128 + n;
        float2 x0 = *reinterpret_cast<const float2*>(x + i0);
        float2 x1 = *reinterpret_cast<const float2*>(x + i1);
        float2 o0, o1;
        o0.x = fmaf(g1, c[j][0] + bb.x, x0.x);
        o0.y = fmaf(g1, c[j][1] + bb.y, x0.y);
        o1.x = fmaf(g1, c[j][2] + bb.x, x1.x);
        o1.y = fmaf(g1, c[j][3] + bb.y, x1.y);
        *reinterpret_cast<float2*>(out + i0) = o0;
        *reinterpret_cast<float2*>(out + i1) = o1;
    }
}

// ---------------- K4: cond-LN -> GELU MLP -> gated residual --------------
__global__ __launch_bounds__(256) void k4_mlp(
    float* __restrict__ out, const float* __restrict__ cvec,
    const float* __restrict__ sw2, const float* __restrict__ sb2,
    const float* __restrict__ bw2, const float* __restrict__ bb2,
    const float* __restrict__ g2w, const float* __restrict__ g2b,
    const float* __restrict__ b1v, const float* __restrict__ b2v)
{
    extern __shared__ float sm[];
    float* HS  = sm;                  // 64*SPAD
    float* M1c = sm + 64 * SPAD;      // 64*SPAD
    float* sS  = sm + 128 * SPAD;     // 3
    int tid = threadIdx.x;
    int to = blockIdx.x * 64;
    int b = to >> 13;

    if (tid < 32) {
        float p0 = dot32(cvec + b * 128, sw2, tid);
        float p1 = dot32(cvec + b * 128, bw2, tid);
        float p2 = dot32(cvec + b * 128, g2w, tid);
        if (tid == 0) {
            sS[0] = p0 + sb2[0];
            sS[1] = p1 + bb2[0];
            sS[2] = p2 + g2b[0];
        }
    }
    __syncthreads();
    float alpha = 1.f + sS[0];
    float b2s = sS[1], g2 = sS[2];

    // LN: 4 threads per token, 32 channels each
    {
        int tt = tid >> 2, q = tid & 3;
        const float4* xp = reinterpret_cast<const float4*>(out + (to + tt) * 128 + q * 32);
        float4 v[8];
#pragma unroll
        for (int i = 0; i < 8; i++) v[i] = xp[i];
        float s = 0.f, ss = 0.f;
#pragma unroll
        for (int i = 0; i < 8; i++) {
            s  += v[i].x + v[i].y + v[i].z + v[i].w;
            ss += v[i].x * v[i].x + v[i].y * v[i].y + v[i].z * v[i].z + v[i].w * v[i].w;
        }
        s  += __shfl_xor_sync(0xffffffffu, s, 1);
        s  += __shfl_xor_sync(0xffffffffu, s, 2);
        ss += __shfl_xor_sync(0xffffffffu, ss, 1);
        ss += __shfl_xor_sync(0xffffffffu, ss, 2);
        float m = s * (1.f / 128.f);
        float rs = rsqrtf(ss * (1.f / 128.f) - m * m + 1e-6f);
        float* hp = &HS[tt * SPAD + q * 32];
#pragma unroll
        for (int i = 0; i < 8; i++) {
            float4 o;
            o.x = cvt_tf32(fmaf(alpha, (v[i].x - m) * rs, b2s));
            o.y = cvt_tf32(fmaf(alpha, (v[i].y - m) * rs, b2s));
            o.z = cvt_tf32(fmaf(alpha, (v[i].z - m) * rs, b2s));
            o.w = cvt_tf32(fmaf(alpha, (v[i].w - m) * rs, b2s));
            *reinterpret_cast<float4*>(hp + i * 4) = o;
        }
    }
    __syncthreads();

    int lane = tid & 31, wid = tid >> 5;
    int g = lane >> 2, t = lane & 3;
    int wm = wid >> 1, wn = wid & 1;
    int row0 = wm * 16, col0 = wn * 64;

    float C2[8][4];
#pragma unroll
    for (int j = 0; j < 8; j++)
#pragma unroll
        for (int e = 0; e < 4; e++) C2[j][e] = 0.f;

    for (int ch = 0; ch < 4; ch++) {
        float c1[8][4];
#pragma unroll
        for (int j = 0; j < 8; j++)
#pragma unroll
            for (int e = 0; e < 4; e++) c1[j][e] = 0.f;
        gemm_16x64_g(HS, g_wimg[5 + ch], row0, wn, lane, g, t, c1);

        __syncthreads();   // prev-chunk gemm2 readers of M1c done
        // gelu -> M1c (tf32)
#pragma unroll
        for (int j = 0; j < 8; j++) {
            int n = col0 + 8 * j + 2 * t;
            int r0 = row0 + g, r1 = r0 + 8;
            float2 bb = *reinterpret_cast<const float2*>(b1v + ch * 128 + n);
            M1c[r0 * SPAD + n]     = cvt_tf32(geluf_(c1[j][0] + bb.x));
            M1c[r0 * SPAD + n + 1] = cvt_tf32(geluf_(c1[j][1] + bb.y));
            M1c[r1 * SPAD + n]     = cvt_tf32(geluf_(c1[j][2] + bb.x));
            M1c[r1 * SPAD + n + 1] = cvt_tf32(geluf_(c1[j][3] + bb.y));
        }
        __syncthreads();
        gemm_16x64_g(M1c, g_wimg[9 + ch], row0, wn, lane, g, t, C2);
    }

    // epilogue (in-place gated residual)
#pragma unroll
    for (int j = 0; j < 8; j++) {
        int n = col0 + 8 * j + 2 * t;
        int r0 = row0 + g, r1 = r0 + 8;
        float2 bb = *reinterpret_cast<const float2*>(b2v + n);
        int i0 = (to + r0) * 128 + n;
        int i1 = (to + r1) * 128 + n;
        float2 x0 = *reinterpret_cast<const float2*>(out + i0);
        float2 x1 = *reinterpret_cast<const float2*>(out + i1);
        float2 o0, o1;
        o0.x = fmaf(g2, C2[j][0] + bb.x, x0.x);
        o0.y = fmaf(g2, C2[j][1] + bb.y, x0.y);
        o1.x = fmaf(g2, C2[j][2] + bb.x, x1.x);
        o1.y = fmaf(g2, C2[j][3] + bb.y, x1.y);
        *reinterpret_cast<float2*>(out + i0) = o0;
        *reinterpret_cast<float2*>(out + i1) = o1;
    }
}

// ---------------- launch -------------------------------------------------
extern "C" void kernel_launch(void* const* d_in, const int* in_sizes, int n_in,
                              void* d_out, int out_size)
{
    const float* x        = (const float*)d_in[0];
    const float* c        = (const float*)d_in[1];
    const float* cln1_sw  = (const float*)d_in[2];
    const float* cln1_sb  = (const float*)d_in[3];
    const float* cln1_bw  = (const float*)d_in[4];
    const float* cln1_bb  = (const float*)d_in[5];
    const float* gate1_w  = (const float*)d_in[6];
    const float* gate1_b  = (const float*)d_in[7];
    const float* rnn_in_w = (const float*)d_in[8];
    const float* rnn_in_b = (const float*)d_in[9];
    const float* pos_emb  = (const float*)d_in[10];
    const float* rnn_wi   = (const float*)d_in[11];
    const float* rnn_bi   = (const float*)d_in[12];
    const float* rnn_wr   = (const float*)d_in[13];
    const float* rnn_br   = (const float*)d_in[14];
    const float* rnn_a    = (const float*)d_in[15];
    const float* rnn_out_w= (const float*)d_in[16];
    const float* rnn_out_b= (const float*)d_in[17];
    const float* cln2_sw  = (const float*)d_in[18];
    const float* cln2_sb  = (const float*)d_in[19];
    const float* cln2_bw  = (const float*)d_in[20];
    const float* cln2_bb  = (const float*)d_in[21];
    const float* gate2_w  = (const float*)d_in[22];
    const float* gate2_b  = (const float*)d_in[23];
    const float* mlp_w1   = (const float*)d_in[24];
    const float* mlp_b1   = (const float*)d_in[25];
    const float* mlp_w2   = (const float*)d_in[26];
    const float* mlp_b2   = (const float*)d_in[27];
    float* out = (float*)d_out;

    const int SM1 = (192 * SPAD + 128 + 2) * 4;       // ~102 KB -> 2 CTAs/SM
    const int SM3 = (128 * SPAD + 4) * 4;             // ~67.6 KB
    const int SM4 = (128 * SPAD + 4) * 4;             // ~67.6 KB
    cudaFuncSetAttribute(k1_pre,      cudaFuncAttributeMaxDynamicSharedMemorySize, SM1);
    cudaFuncSetAttribute(k3_scan_out, cudaFuncAttributeMaxDynamicSharedMemorySize, SM3);
    cudaFuncSetAttribute(k4_mlp,      cudaFuncAttributeMaxDynamicSharedMemorySize, SM4);

    kp_pack<<<13, 256>>>(rnn_in_w, rnn_wi, rnn_wr, rnn_out_w, mlp_w1, mlp_w2);
    k1_pre<<<1024, 256, SM1>>>(x, c, cln1_sw, cln1_sb, cln1_bw, cln1_bb,
                               rnn_in_b, pos_emb, rnn_bi, rnn_br, rnn_a);
    k3_scan_out<<<1024, 256, SM3>>>(x, c, gate1_w, gate1_b, rnn_out_b, out);
    k4_mlp<<<1024, 256, SM4>>>(out, c, cln2_sw, cln2_sb, cln2_bw, cln2_bb,
                               gate2_w, gate2_b, mlp_b1, mlp_b2);
}

// round 11
// speedup vs baseline: 1.3262x; 1.3152x over previous
#include <cuda_runtime.h>
#include <math.h>
#include <stdint.h>

#define BSZ 8
#define SEQ 8192
#define NC  128      // chunks per sequence
#define CS  64       // chunk size == k1 tile size
#define SPAD 132     // 132 mod 32 == 4 -> conflict-free A fragment LDS

// per-wm-pair named barrier (2 warps = 64 threads), ids 1..4
#define BARW(wmv) asm volatile("bar.sync %0, 64;" :: "r"(1 + (wmv)) : "memory")

// ---------------- scratch -----------------------------------------------
__device__ float g_at[BSZ * SEQ * 128];
__device__ float g_bt[BSZ * SEQ * 128];
__device__ float g_stA[2][BSZ][NC][128];
__device__ float g_stB[2][BSZ][NC][128];
// fragment-quad weight images: [seg][kstep(16)][ntpair(8)][lane(32)] float4
// segs: 0 Win, 1 Wi, 2 Wr, 3 WoutF, 4 WoutB, 5-8 W1 chunks, 9-12 W2 chunks
__device__ float4 g_wimg[13][4096];

__device__ __forceinline__ float sigmoidf_(float v) {
    return 1.f / (1.f + expf(-v));
}
__device__ __forceinline__ float geluf_(float v) {
    float u = v + 0.044715f * v * v * v;
    return 0.5f * v * (1.f + tanhf(0.7978845608028654f * u));
}
__device__ __forceinline__ float cvt_tf32(float x) {
    uint32_t u;
    asm("cvt.rna.tf32.f32 %0, %1;" : "=r"(u) : "f"(x));
    return __uint_as_float(u);
}
__device__ __forceinline__ void mma_tf32(float c[4],
    uint32_t a0, uint32_t a1, uint32_t a2, uint32_t a3,
    uint32_t b0, uint32_t b1)
{
    asm("mma.sync.aligned.m16n8k8.row.col.f32.tf32.tf32.f32 "
        "{%0,%1,%2,%3},{%4,%5,%6,%7},{%8,%9},{%0,%1,%2,%3};"
        : "+f"(c[0]), "+f"(c[1]), "+f"(c[2]), "+f"(c[3])
        : "r"(a0), "r"(a1), "r"(a2), "r"(a3), "r"(b0), "r"(b1));
}

// dot(c[128], w[128]) by 32 threads (tid<32); full value in lane 0.
__device__ __forceinline__ float dot32(const float* cvec, const float* w, int tid)
{
    float4 cv = reinterpret_cast<const float4*>(cvec)[tid];
    float4 wv = reinterpret_cast<const float4*>(w)[tid];
    float p = cv.x * wv.x + cv.y * wv.y + cv.z * wv.z + cv.w * wv.w;
    p += __shfl_xor_sync(0xffffffffu, p, 16);
    p += __shfl_xor_sync(0xffffffffu, p, 8);
    p += __shfl_xor_sync(0xffffffffu, p, 4);
    p += __shfl_xor_sync(0xffffffffu, p, 2);
    p += __shfl_xor_sync(0xffffffffu, p, 1);
    return p;
}

// warp computes 16(row) x 64(col) tile of A[..x128] @ W[128x..]; A in smem
// (stride SPAD); B fragment quads streamed from the gmem image with a
// 1-iteration software prefetch (LDG->use distance = one full ks step).
__device__ __forceinline__ void gemm_16x64_g(const float* __restrict__ As,
    const float4* __restrict__ Bimg, int row0, int wn, int lane, int g, int t,
    float c[8][4])
{
    const float4* B0 = Bimg + ((wn * 4) << 5) + lane;
    float4 bv0 = __ldg(B0);
    float4 bv1 = __ldg(B0 + 32);
    float4 bv2 = __ldg(B0 + 64);
    float4 bv3 = __ldg(B0 + 96);
#pragma unroll 4
    for (int ks = 0; ks < 16; ks++) {
        const float* Ar = As + (row0 + g) * SPAD + ks * 8 + t;
        uint32_t a0 = __float_as_uint(Ar[0]);
        uint32_t a2 = __float_as_uint(Ar[4]);
        uint32_t a1 = __float_as_uint(Ar[8 * SPAD]);
        uint32_t a3 = __float_as_uint(Ar[8 * SPAD + 4]);
        float4 bn0, bn1, bn2, bn3;
        if (ks < 15) {
            const float4* Bn = Bimg + (((ks + 1) * 8 + wn * 4) << 5) + lane;
            bn0 = __ldg(Bn);
            bn1 = __ldg(Bn + 32);
            bn2 = __ldg(Bn + 64);
            bn3 = __ldg(Bn + 96);
        }
        mma_tf32(c[0], a0, a1, a2, a3, __float_as_uint(bv0.x), __float_as_uint(bv0.y));
        mma_tf32(c[1], a0, a1, a2, a3, __float_as_uint(bv0.z), __float_as_uint(bv0.w));
        mma_tf32(c[2], a0, a1, a2, a3, __float_as_uint(bv1.x), __float_as_uint(bv1.y));
        mma_tf32(c[3], a0, a1, a2, a3, __float_as_uint(bv1.z), __float_as_uint(bv1.w));
        mma_tf32(c[4], a0, a1, a2, a3, __float_as_uint(bv2.x), __float_as_uint(bv2.y));
        mma_tf32(c[5], a0, a1, a2, a3, __float_as_uint(bv2.z), __float_as_uint(bv2.w));
        mma_tf32(c[6], a0, a1, a2, a3, __float_as_uint(bv3.x), __float_as_uint(bv3.y));
        mma_tf32(c[7], a0, a1, a2, a3, __float_as_uint(bv3.z), __float_as_uint(bv3.w));
        bv0 = bn0; bv1 = bn1; bv2 = bn2; bv3 = bn3;
    }
}

// ---------------- KP: pack all weights into fragment-quad images ---------
__global__ __launch_bounds__(256) void kp_pack(
    const float* __restrict__ Win, const float* __restrict__ Wi,
    const float* __restrict__ Wr,  const float* __restrict__ Wout,
    const float* __restrict__ W1,  const float* __restrict__ W2)
{
    int seg = blockIdx.x;
    const float* src;
    int ns;
    if (seg == 0)      { src = Win;  ns = 128; }
    else if (seg == 1) { src = Wi;   ns = 128; }
    else if (seg == 2) { src = Wr;   ns = 128; }
    else if (seg == 3) { src = Wout; ns = 128; }
    else if (seg == 4) { src = Wout + 128 * 128; ns = 128; }
    else if (seg < 9)  { src = W1 + (seg - 5) * 128; ns = 512; }
    else               { src = W2 + (seg - 9) * 128 * 128; ns = 128; }
    float4* dst = g_wimg[seg];
    for (int p = threadIdx.x; p < 4096; p += 256) {
        int lane = p & 31, ntp = (p >> 5) & 7, ks = p >> 8;
        int g = lane >> 2, t = lane & 3;
        int k = ks * 8 + t, n = ntp * 16 + g;
        dst[p] = make_float4(cvt_tf32(src[k * ns + n]),
                             cvt_tf32(src[(k + 4) * ns + n]),
                             cvt_tf32(src[k * ns + n + 8]),
                             cvt_tf32(src[(k + 4) * ns + n + 8]));
    }
}

// ---------------- K1: LN->LN->(u,gates)->a_t,b_t + chunk states ----------
__global__ __launch_bounds__(256, 2) void k1_pre(
    const float* __restrict__ x,   const float* __restrict__ cvec,
    const float* __restrict__ sw1, const float* __restrict__ sb1,
    const float* __restrict__ bw1, const float* __restrict__ bb1,
    const float* __restrict__ bin, const float* __restrict__ pos,
    const float* __restrict__ bi,  const float* __restrict__ br,
    const float* __restrict__ avec)
{
    extern __shared__ float sm[];
    float* As  = sm;                          // 64*SPAD
    float* ATs = sm + 64 * SPAD;              // 64*SPAD (a_t tile)
    float* BTs = sm + 128 * SPAD;             // 64*SPAD (b_t tile)
    float* L2A = sm + 192 * SPAD;             // 128
    float* sS  = L2A + 128;                   // 2
    int tid = threadIdx.x;
    int blk = blockIdx.x;
    int to  = blk * 64;
    int b   = blk >> 7;
    int ci  = blk & 127;
    int tib = to & (SEQ - 1);

    if (tid < 32) {
        float p0 = dot32(cvec + b * 128, sw1, tid);
        float p1 = dot32(cvec + b * 128, bw1, tid);
        if (tid == 0) { sS[0] = p0 + sb1[0]; sS[1] = p1 + bb1[0]; }
    }
    if (tid >= 128) L2A[tid - 128] = log2f(avec[tid - 128]);
    __syncthreads();
    float alpha = 1.f + sS[0];
    float b1s   = sS[1];

    // ---- LN x2 : 4 threads per token, 32 channels each
    {
        int tt = tid >> 2, q = tid & 3;
        const float4* xp = reinterpret_cast<const float4*>(x + (to + tt) * 128 + q * 32);
        float4 v[8];
#pragma unroll
        for (int i = 0; i < 8; i++) v[i] = xp[i];
        float s = 0.f, ss = 0.f;
#pragma unroll
        for (int i = 0; i < 8; i++) {
            s  += v[i].x + v[i].y + v[i].z + v[i].w;
            ss += v[i].x * v[i].x + v[i].y * v[i].y + v[i].z * v[i].z + v[i].w * v[i].w;
        }
        s  += __shfl_xor_sync(0xffffffffu, s, 1);
        s  += __shfl_xor_sync(0xffffffffu, s, 2);
        ss += __shfl_xor_sync(0xffffffffu, ss, 1);
        ss += __shfl_xor_sync(0xffffffffu, ss, 2);
        float m = s * (1.f / 128.f);
        float rs = rsqrtf(ss * (1.f / 128.f) - m * m + 1e-6f);
        float s2 = 0.f, ss2 = 0.f;
#pragma unroll
        for (int i = 0; i < 8; i++) {
            v[i].x = fmaf(alpha, (v[i].x - m) * rs, b1s);
            v[i].y = fmaf(alpha, (v[i].y - m) * rs, b1s);
            v[i].z = fmaf(alpha, (v[i].z - m) * rs, b1s);
            v[i].w = fmaf(alpha, (v[i].w - m) * rs, b1s);
            s2  += v[i].x + v[i].y + v[i].z + v[i].w;
            ss2 += v[i].x * v[i].x + v[i].y * v[i].y + v[i].z * v[i].z + v[i].w * v[i].w;
        }
        s2  += __shfl_xor_sync(0xffffffffu, s2, 1);
        s2  += __shfl_xor_sync(0xffffffffu, s2, 2);
        ss2 += __shfl_xor_sync(0xffffffffu, ss2, 1);
        ss2 += __shfl_xor_sync(0xffffffffu, ss2, 2);
        float m2 = s2 * (1.f / 128.f);
        float rs2 = rsqrtf(ss2 * (1.f / 128.f) - m2 * m2 + 1e-6f);
        float* Ap = &As[tt * SPAD + q * 32];
#pragma unroll
        for (int i = 0; i < 8; i++) {
            float4 o;
            o.x = cvt_tf32((v[i].x - m2) * rs2);
            o.y = cvt_tf32((v[i].y - m2) * rs2);
            o.z = cvt_tf32((v[i].z - m2) * rs2);
            o.w = cvt_tf32((v[i].w - m2) * rs2);
            *reinterpret_cast<float4*>(Ap + i * 4) = o;
        }
    }
    __syncthreads();

    int lane = tid & 31, wid = tid >> 5;
    int g = lane >> 2, t = lane & 3;
    int wm = wid >> 1, wn = wid & 1;
    int row0 = wm * 16, col0 = wn * 64;

    // GEMM1: u = ln2h @ Win
    float c1[8][4];
#pragma unroll
    for (int j = 0; j < 8; j++)
#pragma unroll
        for (int e = 0; e < 4; e++) c1[j][e] = 0.f;
    gemm_16x64_g(As, g_wimg[0], row0, wn, lane, g, t, c1);
    BARW(wm);   // As rows [row0,row0+16) touched only by this wm pair

    // u = c1 + bin + pos -> back into As (tf32)
#pragma unroll
    for (int j = 0; j < 8; j++) {
        int n = col0 + 8 * j + 2 * t;
        int r0 = row0 + g, r1 = r0 + 8;
        float2 bb = *reinterpret_cast<const float2*>(bin + n);
        float2 p0 = *reinterpret_cast<const float2*>(pos + (tib + r0) * 128 + n);
        float2 p1 = *reinterpret_cast<const float2*>(pos + (tib + r1) * 128 + n);
        As[r0 * SPAD + n]     = cvt_tf32(c1[j][0] + bb.x + p0.x);
        As[r0 * SPAD + n + 1] = cvt_tf32(c1[j][1] + bb.y + p0.y);
        As[r1 * SPAD + n]     = cvt_tf32(c1[j][2] + bb.x + p1.x);
        As[r1 * SPAD + n + 1] = cvt_tf32(c1[j][3] + bb.y + p1.y);
    }
    BARW(wm);

    // GEMM2: input gate
    float gi[8][4];
#pragma unroll
    for (int j = 0; j < 8; j++)
#pragma unroll
        for (int e = 0; e < 4; e++) gi[j][e] = 0.f;
    gemm_16x64_g(As, g_wimg[1], row0, wn, lane, g, t, gi);
#pragma unroll
    for (int j = 0; j < 8; j++) {
        int n = col0 + 8 * j + 2 * t;
        float2 bb = *reinterpret_cast<const float2*>(bi + n);
        gi[j][0] = sigmoidf_(gi[j][0] + bb.x);
        gi[j][1] = sigmoidf_(gi[j][1] + bb.y);
        gi[j][2] = sigmoidf_(gi[j][2] + bb.x);
        gi[j][3] = sigmoidf_(gi[j][3] + bb.y);
    }

    // GEMM3: recurrence gate (As unchanged, no sync needed)
#pragma unroll
    for (int j = 0; j < 8; j++)
#pragma unroll
        for (int e = 0; e < 4; e++) c1[j][e] = 0.f;
    gemm_16x64_g(As, g_wimg[2], row0, wn, lane, g, t, c1);

    // epilogue: a_t, b_t -> gmem AND smem tiles
#pragma unroll
    for (int j = 0; j < 8; j++) {
        int n = col0 + 8 * j + 2 * t;
        int r0 = row0 + g, r1 = r0 + 8;
        float2 bb = *reinterpret_cast<const float2*>(br + n);
        float la0 = L2A[n], la1 = L2A[n + 1];
        float u00 = As[r0 * SPAD + n], u01 = As[r0 * SPAD + n + 1];
        float u10 = As[r1 * SPAD + n], u11 = As[r1 * SPAD + n + 1];
        float at00 = exp2f(8.f * sigmoidf_(c1[j][0] + bb.x) * la0);
        float at01 = exp2f(8.f * sigmoidf_(c1[j][1] + bb.y) * la1);
        float at10 = exp2f(8.f * sigmoidf_(c1[j][2] + bb.x) * la0);
        float at11 = exp2f(8.f * sigmoidf_(c1[j][3] + bb.y) * la1);
        float bt00 = sqrtf(fmaxf(1.f - at00 * at00, 0.f)) * gi[j][0] * u00;
        float bt01 = sqrtf(fmaxf(1.f - at01 * at01, 0.f)) * gi[j][1] * u01;
        float bt10 = sqrtf(fmaxf(1.f - at10 * at10, 0.f)) * gi[j][2] * u10;
        float bt11 = sqrtf(fmaxf(1.f - at11 * at11, 0.f)) * gi[j][3] * u11;
        int i0 = (to + r0) * 128 + n;
        int i1 = (to + r1) * 128 + n;
        *reinterpret_cast<float2*>(g_at + i0) = make_float2(at00, at01);
        *reinterpret_cast<float2*>(g_at + i1) = make_float2(at10, at11);
        *reinterpret_cast<float2*>(g_bt + i0) = make_float2(bt00, bt01);
        *reinterpret_cast<float2*>(g_bt + i1) = make_float2(bt10, bt11);
        *reinterpret_cast<float2*>(&ATs[r0 * SPAD + n]) = make_float2(at00, at01);
        *reinterpret_cast<float2*>(&ATs[r1 * SPAD + n]) = make_float2(at10, at11);
        *reinterpret_cast<float2*>(&BTs[r0 * SPAD + n]) = make_float2(bt00, bt01);
        *reinterpret_cast<float2*>(&BTs[r1 * SPAD + n]) = make_float2(bt10, bt11);
    }
    __syncthreads();

    // fused chunk-state fold (was k2a): 2 dirs x 128 channels
    {
        int dir = tid >> 7, h = tid & 127;
        float Ap = 1.f, Bv = 0.f;
        if (dir == 0) {
#pragma unroll 8
            for (int s = 0; s < CS; s++) {
                float a = ATs[s * SPAD + h], bb = BTs[s * SPAD + h];
                Ap *= a;
                Bv = fmaf(a, Bv, bb);
            }
        } else {
#pragma unroll 8
            for (int s = CS - 1; s >= 0; s--) {
                float a = ATs[s * SPAD + h], bb = BTs[s * SPAD + h];
                Ap *= a;
                Bv = fmaf(a, Bv, bb);
            }
        }
        g_stA[dir][b][ci][h] = Ap;
        g_stB[dir][b][ci][h] = Bv;
    }
}

// ---------------- K3: prefix + re-scan + out-GEMM + residual -------------
__global__ __launch_bounds__(256, 2) void k3_scan_out(
    const float* __restrict__ x, const float* __restrict__ cvec,
    const float* __restrict__ g1w, const float* __restrict__ g1b,
    const float* __restrict__ bout, float* __restrict__ out)
{
    extern __shared__ float sm[];
    float* HF = sm;                 // 64*SPAD
    float* HB = sm + 64 * SPAD;     // 64*SPAD
    float* sG = sm + 128 * SPAD;    // 1
    int blk = blockIdx.x;
    int b = blk >> 7, ci = blk & 127;
    int tid = threadIdx.x;

    if (tid < 32) {
        float p = dot32(cvec + b * 128, g1w, tid);
        if (tid == 0) sG[0] = p + g1b[0];
    }
    {
        int dir = tid >> 7, h = tid & 127;
        // batched prefix fold over predecessor chunk states
        float hc = 0.f;
        if (dir == 0) {
            int j = 0;
            while (j < ci) {
                int nb = ci - j; if (nb > 16) nb = 16;
                float av[16], bv[16];
#pragma unroll
                for (int q = 0; q < 16; q++)
                    if (q < nb) {
                        av[q] = g_stA[0][b][j + q][h];
                        bv[q] = g_stB[0][b][j + q][h];
                    }
#pragma unroll
                for (int q = 0; q < 16; q++)
                    if (q < nb) hc = fmaf(av[q], hc, bv[q]);
                j += nb;
            }
        } else {
            int j = NC - 1;
            while (j > ci) {
                int nb = j - ci; if (nb > 16) nb = 16;
                float av[16], bv[16];
#pragma unroll
                for (int q = 0; q < 16; q++)
                    if (q < nb) {
                        av[q] = g_stA[1][b][j - q][h];
                        bv[q] = g_stB[1][b][j - q][h];
                    }
#pragma unroll
                for (int q = 0; q < 16; q++)
                    if (q < nb) hc = fmaf(av[q], hc, bv[q]);
                j -= nb;
            }
        }
        // chunk re-scan with batched prefetch (MLP ~16)
        int base = ((b << 13) + (ci << 6)) * 128 + h;
        if (dir == 0) {
            for (int s0 = 0; s0 < CS; s0 += 8) {
                float av[8], bv[8];
#pragma unroll
                for (int q = 0; q < 8; q++) {
                    int idx = base + ((s0 + q) << 7);
                    av[q] = g_at[idx];
                    bv[q] = g_bt[idx];
                }
#pragma unroll
                for (int q = 0; q < 8; q++) {
                    hc = fmaf(av[q], hc, bv[q]);
                    HF[(s0 + q) * SPAD + h] = cvt_tf32(hc);
                }
            }
        } else {
            for (int s0 = CS - 1; s0 >= 0; s0 -= 8) {
                float av[8], bv[8];
#pragma unroll
                for (int q = 0; q < 8; q++) {
                    int idx = base + ((s0 - q) << 7);
                    av[q] = g_at[idx];
                    bv[q] = g_bt[idx];
                }
#pragma unroll
                for (int q = 0; q < 8; q++) {
                    hc = fmaf(av[q], hc, bv[q]);
                    HB[(s0 - q) * SPAD + h] = cvt_tf32(hc);
                }
            }
        }
    }
    __syncthreads();

    int lane = tid & 31, wid = tid >> 5;
    int g = lane >> 2, t = lane & 3;
    int wm = wid >> 1, wn = wid & 1;
    int row0 = wm * 16, col0 = wn * 64;
    float c[8][4];
#pragma unroll
    for (int j = 0; j < 8; j++)
#pragma unroll
        for (int e = 0; e < 4; e++) c[j][e] = 0.f;
    gemm_16x64_g(HF, g_wimg[3], row0, wn, lane, g, t, c);
    gemm_16x64_g(HB, g_wimg[4], row0, wn, lane, g, t, c);

    float g1 = sG[0];
    int tbase = (b << 13) + (ci << 6);
#pragma unroll
    for (int j = 0; j < 8; j++) {
        int n = col0 + 8 * j + 2 * t;
        int r0 = row0 + g, r1 = r0 + 8;
        float2 bb = *reinterpret_cast<const float2*>(bout + n);
        int i0 = (tbase + r0) * 128 + n;
        int i1 = (tbase + r1) * 128 + n;
        float2 x0 = *reinterpret_cast<const float2*>(x + i0);
        float2 x1 = *reinterpret_cast<const float2*>(x + i1);
        float2 o0, o1;
        o0.x = fmaf(g1, c[j][0] + bb.x, x0.x);
        o0.y = fmaf(g1, c[j][1] + bb.y, x0.y);
        o1.x = fmaf(g1, c[j][2] + bb.x, x1.x);
        o1.y = fmaf(g1, c[j][3] + bb.y, x1.y);
        *reinterpret_cast<float2*>(out + i0) = o0;
        *reinterpret_cast<float2*>(out + i1) = o1;
    }
}

// ---------------- K4: cond-LN -> GELU MLP -> gated residual --------------
__global__ __launch_bounds__(256, 2) void k4_mlp(
    float* __restrict__ out, const float* __restrict__ cvec,
    const float* __restrict__ sw2, const float* __restrict__ sb2,
    const float* __restrict__ bw2, const float* __restrict__ bb2,
    const float* __restrict__ g2w, const float* __restrict__ g2b,
    const float* __restrict__ b1v, const float* __restrict__ b2v)
{
    extern __shared__ float sm[];
    float* HS  = sm;                  // 64*SPAD
    float* M1c = sm + 64 * SPAD;      // 64*SPAD
    float* sS  = sm + 128 * SPAD;     // 3
    int tid = threadIdx.x;
    int to = blockIdx.x * 64;
    int b = to >> 13;

    if (tid < 32) {
        float p0 = dot32(cvec + b * 128, sw2, tid);
        float p1 = dot32(cvec + b * 128, bw2, tid);
        float p2 = dot32(cvec + b * 128, g2w, tid);
        if (tid == 0) {
            sS[0] = p0 + sb2[0];
            sS[1] = p1 + bb2[0];
            sS[2] = p2 + g2b[0];
        }
    }
    __syncthreads();
    float alpha = 1.f + sS[0];
    float b2s = sS[1], g2 = sS[2];

    // LN: 4 threads per token, 32 channels each
    {
        int tt = tid >> 2, q = tid & 3;
        const float4* xp = reinterpret_cast<const float4*>(out + (to + tt) * 128 + q * 32);
        float4 v[8];
#pragma unroll
        for (int i = 0; i < 8; i++) v[i] = xp[i];
        float s = 0.f, ss = 0.f;
#pragma unroll
        for (int i = 0; i < 8; i++) {
            s  += v[i].x + v[i].y + v[i].z + v[i].w;
            ss += v[i].x * v[i].x + v[i].y * v[i].y + v[i].z * v[i].z + v[i].w * v[i].w;
        }
        s  += __shfl_xor_sync(0xffffffffu, s, 1);
        s  += __shfl_xor_sync(0xffffffffu, s, 2);
        ss += __shfl_xor_sync(0xffffffffu, ss, 1);
        ss += __shfl_xor_sync(0xffffffffu, ss, 2);
        float m = s * (1.f / 128.f);
        float rs = rsqrtf(ss * (1.f / 128.f) - m * m + 1e-6f);
        float* hp = &HS[tt * SPAD + q * 32];
#pragma unroll
        for (int i = 0; i < 8; i++) {
            float4 o;
            o.x = cvt_tf32(fmaf(alpha, (v[i].x - m) * rs, b2s));
            o.y = cvt_tf32(fmaf(alpha, (v[i].y - m) * rs, b2s));
            o.z = cvt_tf32(fmaf(alpha, (v[i].z - m) * rs, b2s));
            o.w = cvt_tf32(fmaf(alpha, (v[i].w - m) * rs, b2s));
            *reinterpret_cast<float4*>(hp + i * 4) = o;
        }
    }
    __syncthreads();

    int lane = tid & 31, wid = tid >> 5;
    int g = lane >> 2, t = lane & 3;
    int wm = wid >> 1, wn = wid & 1;
    int row0 = wm * 16, col0 = wn * 64;

    float C2[8][4];
#pragma unroll
    for (int j = 0; j < 8; j++)
#pragma unroll
        for (int e = 0; e < 4; e++) C2[j][e] = 0.f;

    for (int ch = 0; ch < 4; ch++) {
        float c1[8][4];
#pragma unroll
        for (int j = 0; j < 8; j++)
#pragma unroll
            for (int e = 0; e < 4; e++) c1[j][e] = 0.f;
        gemm_16x64_g(HS, g_wimg[5 + ch], row0, wn, lane, g, t, c1);

        BARW(wm);   // prev-chunk gemm2 readers of this wm's M1c rows done
        // gelu -> M1c (tf32)
#pragma unroll
        for (int j = 0; j < 8; j++) {
            int n = col0 + 8 * j + 2 * t;
            int r0 = row0 + g, r1 = r0 + 8;
            float2 bb = *reinterpret_cast<const float2*>(b1v + ch * 128 + n);
            M1c[r0 * SPAD + n]     = cvt_tf32(geluf_(c1[j][0] + bb.x));
            M1c[r0 * SPAD + n + 1] = cvt_tf32(geluf_(c1[j][1] + bb.y));
            M1c[r1 * SPAD + n]     = cvt_tf32(geluf_(c1[j][2] + bb.x));
            M1c[r1 * SPAD + n + 1] = cvt_tf32(geluf_(c1[j][3] + bb.y));
        }
        BARW(wm);
        gemm_16x64_g(M1c, g_wimg[9 + ch], row0, wn, lane, g, t, C2);
    }

    // epilogue (in-place gated residual)
#pragma unroll
    for (int j = 0; j < 8; j++) {
        int n = col0 + 8 * j + 2 * t;
        int r0 = row0 + g, r1 = r0 + 8;
        float2 bb = *reinterpret_cast<const float2*>(b2v + n);
        int i0 = (to + r0) * 128 + n;
        int i1 = (to + r1) * 128 + n;
        float2 x0 = *reinterpret_cast<const float2*>(out + i0);
        float2 x1 = *reinterpret_cast<const float2*>(out + i1);
        float2 o0, o1;
        o0.x = fmaf(g2, C2[j][0] + bb.x, x0.x);
        o0.y = fmaf(g2, C2[j][1] + bb.y, x0.y);
        o1.x = fmaf(g2, C2[j][2] + bb.x, x1.x);
        o1.y = fmaf(g2, C2[j][3] + bb.y, x1.y);
        *reinterpret_cast<float2*>(out + i0) = o0;
        *reinterpret_cast<float2*>(out + i1) = o1;
    }
}

// ---------------- launch -------------------------------------------------
extern "C" void kernel_launch(void* const* d_in, const int* in_sizes, int n_in,
                              void* d_out, int out_size)
{
    const float* x        = (const float*)d_in[0];
    const float* c        = (const float*)d_in[1];
    const float* cln1_sw  = (const float*)d_in[2];
    const float* cln1_sb  = (const float*)d_in[3];
    const float* cln1_bw  = (const float*)d_in[4];
    const float* cln1_bb  = (const float*)d_in[5];
    const float* gate1_w  = (const float*)d_in[6];
    const float* gate1_b  = (const float*)d_in[7];
    const float* rnn_in_w = (const float*)d_in[8];
    const float* rnn_in_b = (const float*)d_in[9];
    const float* pos_emb  = (const float*)d_in[10];
    const float* rnn_wi   = (const float*)d_in[11];
    const float* rnn_bi   = (const float*)d_in[12];
    const float* rnn_wr   = (const float*)d_in[13];
    const float* rnn_br   = (const float*)d_in[14];
    const float* rnn_a    = (const float*)d_in[15];
    const float* rnn_out_w= (const float*)d_in[16];
    const float* rnn_out_b= (const float*)d_in[17];
    const float* cln2_sw  = (const float*)d_in[18];
    const float* cln2_sb  = (const float*)d_in[19];
    const float* cln2_bw  = (const float*)d_in[20];
    const float* cln2_bb  = (const float*)d_in[21];
    const float* gate2_w  = (const float*)d_in[22];
    const float* gate2_b  = (const float*)d_in[23];
    const float* mlp_w1   = (const float*)d_in[24];
    const float* mlp_b1   = (const float*)d_in[25];
    const float* mlp_w2   = (const float*)d_in[26];
    const float* mlp_b2   = (const float*)d_in[27];
    float* out = (float*)d_out;

    const int SM1 = (192 * SPAD + 128 + 2) * 4;       // ~102 KB -> 2 CTAs/SM
    const int SM3 = (128 * SPAD + 4) * 4;             // ~67.6 KB
    const int SM4 = (128 * SPAD + 4) * 4;             // ~67.6 KB
    cudaFuncSetAttribute(k1_pre,      cudaFuncAttributeMaxDynamicSharedMemorySize, SM1);
    cudaFuncSetAttribute(k3_scan_out, cudaFuncAttributeMaxDynamicSharedMemorySize, SM3);
    cudaFuncSetAttribute(k4_mlp,      cudaFuncAttributeMaxDynamicSharedMemorySize, SM4);

    kp_pack<<<13, 256>>>(rnn_in_w, rnn_wi, rnn_wr, rnn_out_w, mlp_w1, mlp_w2);
    k1_pre<<<1024, 256, SM1>>>(x, c, cln1_sw, cln1_sb, cln1_bw, cln1_bb,
                               rnn_in_b, pos_emb, rnn_bi, rnn_br, rnn_a);
    k3_scan_out<<<1024, 256, SM3>>>(x, c, gate1_w, gate1_b, rnn_out_b, out);
    k4_mlp<<<1024, 256, SM4>>>(out, c, cln2_sw, cln2_sb, cln2_bw, cln2_bb,
                               gate2_w, gate2_b, mlp_b1, mlp_b2);
}

// round 14
// speedup vs baseline: 1.3776x; 1.0388x over previous
#include <cuda_runtime.h>
#include <math.h>
#include <stdint.h>

#define BSZ 8
#define SEQ 8192
#define NC  128      // chunks per sequence
#define CS  64       // chunk size == tile size
#define SPAD 132     // 132 mod 32 == 4 -> conflict-free A fragment LDS

// per-wm-pair named barrier (2 warps = 64 threads), ids 1..4
#define BARW(wmv) asm volatile("bar.sync %0, 64;" :: "r"(1 + (wmv)) : "memory")

// ---------------- scratch -----------------------------------------------
__device__ float g_at[BSZ * SEQ * 128];
__device__ float g_bt[BSZ * SEQ * 128];
__device__ float g_stA[2][BSZ][NC][128];
__device__ float g_stB[2][BSZ][NC][128];
// fragment-quad weight images: [seg][kstep(16)][ntpair(8)][lane(32)] float4
// segs: 0 Win, 1 Wi, 2 Wr, 3 WoutF, 4 WoutB, 5-8 W1 chunks, 9-12 W2 chunks
__device__ float4 g_wimg[13][4096];

__device__ __forceinline__ float sigmoidf_(float v) {
    return 1.f / (1.f + expf(-v));
}
__device__ __forceinline__ float geluf_(float v) {
    float u = v + 0.044715f * v * v * v;
    return 0.5f * v * (1.f + tanhf(0.7978845608028654f * u));
}
__device__ __forceinline__ float cvt_tf32(float x) {
    uint32_t u;
    asm("cvt.rna.tf32.f32 %0, %1;" : "=r"(u) : "f"(x));
    return __uint_as_float(u);
}
__device__ __forceinline__ void mma_tf32(float c[4],
    uint32_t a0, uint32_t a1, uint32_t a2, uint32_t a3,
    uint32_t b0, uint32_t b1)
{
    asm("mma.sync.aligned.m16n8k8.row.col.f32.tf32.tf32.f32 "
        "{%0,%1,%2,%3},{%4,%5,%6,%7},{%8,%9},{%0,%1,%2,%3};"
        : "+f"(c[0]), "+f"(c[1]), "+f"(c[2]), "+f"(c[3])
        : "r"(a0), "r"(a1), "r"(a2), "r"(a3), "r"(b0), "r"(b1));
}

// dot(c[128], w[128]) by 32 threads (tid<32); full value in lane 0.
__device__ __forceinline__ float dot32(const float* cvec, const float* w, int tid)
{
    float4 cv = reinterpret_cast<const float4*>(cvec)[tid];
    float4 wv = reinterpret_cast<const float4*>(w)[tid];
    float p = cv.x * wv.x + cv.y * wv.y + cv.z * wv.z + cv.w * wv.w;
    p += __shfl_xor_sync(0xffffffffu, p, 16);
    p += __shfl_xor_sync(0xffffffffu, p, 8);
    p += __shfl_xor_sync(0xffffffffu, p, 4);
    p += __shfl_xor_sync(0xffffffffu, p, 2);
    p += __shfl_xor_sync(0xffffffffu, p, 1);
    return p;
}

// warp computes 16(row) x 64(col) tile of A[..x128] @ W[128x..]; A in smem
// (stride SPAD); B fragment quads streamed from the gmem image with a
// 1-iteration software prefetch (LDG->use distance = one full ks step).
__device__ __forceinline__ void gemm_16x64_g(const float* __restrict__ As,
    const float4* __restrict__ Bimg, int row0, int wn, int lane, int g, int t,
    float c[8][4])
{
    const float4* B0 = Bimg + ((wn * 4) << 5) + lane;
    float4 bv0 = __ldg(B0);
    float4 bv1 = __ldg(B0 + 32);
    float4 bv2 = __ldg(B0 + 64);
    float4 bv3 = __ldg(B0 + 96);
#pragma unroll 4
    for (int ks = 0; ks < 16; ks++) {
        const float* Ar = As + (row0 + g) * SPAD + ks * 8 + t;
        uint32_t a0 = __float_as_uint(Ar[0]);
        uint32_t a2 = __float_as_uint(Ar[4]);
        uint32_t a1 = __float_as_uint(Ar[8 * SPAD]);
        uint32_t a3 = __float_as_uint(Ar[8 * SPAD + 4]);
        float4 bn0, bn1, bn2, bn3;
        if (ks < 15) {
            const float4* Bn = Bimg + (((ks + 1) * 8 + wn * 4) << 5) + lane;
            bn0 = __ldg(Bn);
            bn1 = __ldg(Bn + 32);
            bn2 = __ldg(Bn + 64);
            bn3 = __ldg(Bn + 96);
        }
        mma_tf32(c[0], a0, a1, a2, a3, __float_as_uint(bv0.x), __float_as_uint(bv0.y));
        mma_tf32(c[1], a0, a1, a2, a3, __float_as_uint(bv0.z), __float_as_uint(bv0.w));
        mma_tf32(c[2], a0, a1, a2, a3, __float_as_uint(bv1.x), __float_as_uint(bv1.y));
        mma_tf32(c[3], a0, a1, a2, a3, __float_as_uint(bv1.z), __float_as_uint(bv1.w));
        mma_tf32(c[4], a0, a1, a2, a3, __float_as_uint(bv2.x), __float_as_uint(bv2.y));
        mma_tf32(c[5], a0, a1, a2, a3, __float_as_uint(bv2.z), __float_as_uint(bv2.w));
        mma_tf32(c[6], a0, a1, a2, a3, __float_as_uint(bv3.x), __float_as_uint(bv3.y));
        mma_tf32(c[7], a0, a1, a2, a3, __float_as_uint(bv3.z), __float_as_uint(bv3.w));
        bv0 = bn0; bv1 = bn1; bv2 = bn2; bv3 = bn3;
    }
}

// ---------------- KP: pack all weights into fragment-quad images ---------
__global__ __launch_bounds__(256) void kp_pack(
    const float* __restrict__ Win, const float* __restrict__ Wi,
    const float* __restrict__ Wr,  const float* __restrict__ Wout,
    const float* __restrict__ W1,  const float* __restrict__ W2)
{
    int seg = blockIdx.x;
    const float* src;
    int ns;
    if (seg == 0)      { src = Win;  ns = 128; }
    else if (seg == 1) { src = Wi;   ns = 128; }
    else if (seg == 2) { src = Wr;   ns = 128; }
    else if (seg == 3) { src = Wout; ns = 128; }
    else if (seg == 4) { src = Wout + 128 * 128; ns = 128; }
    else if (seg < 9)  { src = W1 + (seg - 5) * 128; ns = 512; }
    else               { src = W2 + (seg - 9) * 128 * 128; ns = 128; }
    float4* dst = g_wimg[seg];
    for (int p = threadIdx.x; p < 4096; p += 256) {
        int lane = p & 31, ntp = (p >> 5) & 7, ks = p >> 8;
        int g = lane >> 2, t = lane & 3;
        int k = ks * 8 + t, n = ntp * 16 + g;
        dst[p] = make_float4(cvt_tf32(src[k * ns + n]),
                             cvt_tf32(src[(k + 4) * ns + n]),
                             cvt_tf32(src[k * ns + n + 8]),
                             cvt_tf32(src[(k + 4) * ns + n + 8]));
    }
}

// ---------------- K1: LN->LN->(u,gates)->a_t,b_t + chunk states ----------
__global__ __launch_bounds__(256, 2) void k1_pre(
    const float* __restrict__ x,   const float* __restrict__ cvec,
    const float* __restrict__ sw1, const float* __restrict__ sb1,
    const float* __restrict__ bw1, const float* __restrict__ bb1,
    const float* __restrict__ bin, const float* __restrict__ pos,
    const float* __restrict__ bi,  const float* __restrict__ br,
    const float* __restrict__ avec)
{
    extern __shared__ float sm[];
    float* As  = sm;                          // 64*SPAD
    float* ATs = sm + 64 * SPAD;              // 64*SPAD (a_t tile)
    float* BTs = sm + 128 * SPAD;             // 64*SPAD (b_t tile)
    float* L2A = sm + 192 * SPAD;             // 128
    float* sS  = L2A + 128;                   // 2
    int tid = threadIdx.x;
    int blk = blockIdx.x;
    int to  = blk * 64;
    int b   = blk >> 7;
    int ci  = blk & 127;
    int tib = to & (SEQ - 1);

    if (tid < 32) {
        float p0 = dot32(cvec + b * 128, sw1, tid);
        float p1 = dot32(cvec + b * 128, bw1, tid);
        if (tid == 0) { sS[0] = p0 + sb1[0]; sS[1] = p1 + bb1[0]; }
    }
    if (tid >= 128) L2A[tid - 128] = log2f(avec[tid - 128]);
    __syncthreads();
    float alpha = 1.f + sS[0];
    float b1s   = sS[1];

    // ---- LN x2 : 4 threads per token, 32 channels each
    {
        int tt = tid >> 2, q = tid & 3;
        const float4* xp = reinterpret_cast<const float4*>(x + (to + tt) * 128 + q * 32);
        float4 v[8];
#pragma unroll
        for (int i = 0; i < 8; i++) v[i] = xp[i];
        float s = 0.f, ss = 0.f;
#pragma unroll
        for (int i = 0; i < 8; i++) {
            s  += v[i].x + v[i].y + v[i].z + v[i].w;
            ss += v[i].x * v[i].x + v[i].y * v[i].y + v[i].z * v[i].z + v[i].w * v[i].w;
        }
        s  += __shfl_xor_sync(0xffffffffu, s, 1);
        s  += __shfl_xor_sync(0xffffffffu, s, 2);
        ss += __shfl_xor_sync(0xffffffffu, ss, 1);
        ss += __shfl_xor_sync(0xffffffffu, ss, 2);
        float m = s * (1.f / 128.f);
        float rs = rsqrtf(ss * (1.f / 128.f) - m * m + 1e-6f);
        float s2 = 0.f, ss2 = 0.f;
#pragma unroll
        for (int i = 0; i < 8; i++) {
            v[i].x = fmaf(alpha, (v[i].x - m) * rs, b1s);
            v[i].y = fmaf(alpha, (v[i].y - m) * rs, b1s);
            v[i].z = fmaf(alpha, (v[i].z - m) * rs, b1s);
            v[i].w = fmaf(alpha, (v[i].w - m) * rs, b1s);
            s2  += v[i].x + v[i].y + v[i].z + v[i].w;
            ss2 += v[i].x * v[i].x + v[i].y * v[i].y + v[i].z * v[i].z + v[i].w * v[i].w;
        }
        s2  += __shfl_xor_sync(0xffffffffu, s2, 1);
        s2  += __shfl_xor_sync(0xffffffffu, s2, 2);
        ss2 += __shfl_xor_sync(0xffffffffu, ss2, 1);
        ss2 += __shfl_xor_sync(0xffffffffu, ss2, 2);
        float m2 = s2 * (1.f / 128.f);
        float rs2 = rsqrtf(ss2 * (1.f / 128.f) - m2 * m2 + 1e-6f);
        float* Ap = &As[tt * SPAD + q * 32];
#pragma unroll
        for (int i = 0; i < 8; i++) {
            float4 o;
            o.x = cvt_tf32((v[i].x - m2) * rs2);
            o.y = cvt_tf32((v[i].y - m2) * rs2);
            o.z = cvt_tf32((v[i].z - m2) * rs2);
            o.w = cvt_tf32((v[i].w - m2) * rs2);
            *reinterpret_cast<float4*>(Ap + i * 4) = o;
        }
    }
    __syncthreads();

    int lane = tid & 31, wid = tid >> 5;
    int g = lane >> 2, t = lane & 3;
    int wm = wid >> 1, wn = wid & 1;
    int row0 = wm * 16, col0 = wn * 64;

    // GEMM1: u = ln2h @ Win
    float c1[8][4];
#pragma unroll
    for (int j = 0; j < 8; j++)
#pragma unroll
        for (int e = 0; e < 4; e++) c1[j][e] = 0.f;
    gemm_16x64_g(As, g_wimg[0], row0, wn, lane, g, t, c1);
    BARW(wm);   // As rows [row0,row0+16) touched only by this wm pair

    // u = c1 + bin + pos -> back into As (tf32)
#pragma unroll
    for (int j = 0; j < 8; j++) {
        int n = col0 + 8 * j + 2 * t;
        int r0 = row0 + g, r1 = r0 + 8;
        float2 bb = *reinterpret_cast<const float2*>(bin + n);
        float2 p0 = *reinterpret_cast<const float2*>(pos + (tib + r0) * 128 + n);
        float2 p1 = *reinterpret_cast<const float2*>(pos + (tib + r1) * 128 + n);
        As[r0 * SPAD + n]     = cvt_tf32(c1[j][0] + bb.x + p0.x);
        As[r0 * SPAD + n + 1] = cvt_tf32(c1[j][1] + bb.y + p0.y);
        As[r1 * SPAD + n]     = cvt_tf32(c1[j][2] + bb.x + p1.x);
        As[r1 * SPAD + n + 1] = cvt_tf32(c1[j][3] + bb.y + p1.y);
    }
    BARW(wm);

    // GEMM2: input gate
    float gi[8][4];
#pragma unroll
    for (int j = 0; j < 8; j++)
#pragma unroll
        for (int e = 0; e < 4; e++) gi[j][e] = 0.f;
    gemm_16x64_g(As, g_wimg[1], row0, wn, lane, g, t, gi);
#pragma unroll
    for (int j = 0; j < 8; j++) {
        int n = col0 + 8 * j + 2 * t;
        float2 bb = *reinterpret_cast<const float2*>(bi + n);
        gi[j][0] = sigmoidf_(gi[j][0] + bb.x);
        gi[j][1] = sigmoidf_(gi[j][1] + bb.y);
        gi[j][2] = sigmoidf_(gi[j][2] + bb.x);
        gi[j][3] = sigmoidf_(gi[j][3] + bb.y);
    }

    // GEMM3: recurrence gate (As unchanged, no sync needed)
#pragma unroll
    for (int j = 0; j < 8; j++)
#pragma unroll
        for (int e = 0; e < 4; e++) c1[j][e] = 0.f;
    gemm_16x64_g(As, g_wimg[2], row0, wn, lane, g, t, c1);

    // epilogue: a_t, b_t -> gmem AND smem tiles
#pragma unroll
    for (int j = 0; j < 8; j++) {
        int n = col0 + 8 * j + 2 * t;
        int r0 = row0 + g, r1 = r0 + 8;
        float2 bb = *reinterpret_cast<const float2*>(br + n);
        float la0 = L2A[n], la1 = L2A[n + 1];
        float u00 = As[r0 * SPAD + n], u01 = As[r0 * SPAD + n + 1];
        float u10 = As[r1 * SPAD + n], u11 = As[r1 * SPAD + n + 1];
        float at00 = exp2f(8.f * sigmoidf_(c1[j][0] + bb.x) * la0);
        float at01 = exp2f(8.f * sigmoidf_(c1[j][1] + bb.y) * la1);
        float at10 = exp2f(8.f * sigmoidf_(c1[j][2] + bb.x) * la0);
        float at11 = exp2f(8.f * sigmoidf_(c1[j][3] + bb.y) * la1);
        float bt00 = sqrtf(fmaxf(1.f - at00 * at00, 0.f)) * gi[j][0] * u00;
        float bt01 = sqrtf(fmaxf(1.f - at01 * at01, 0.f)) * gi[j][1] * u01;
        float bt10 = sqrtf(fmaxf(1.f - at10 * at10, 0.f)) * gi[j][2] * u10;
        float bt11 = sqrtf(fmaxf(1.f - at11 * at11, 0.f)) * gi[j][3] * u11;
        int i0 = (to + r0) * 128 + n;
        int i1 = (to + r1) * 128 + n;
        *reinterpret_cast<float2*>(g_at + i0) = make_float2(at00, at01);
        *reinterpret_cast<float2*>(g_at + i1) = make_float2(at10, at11);
        *reinterpret_cast<float2*>(g_bt + i0) = make_float2(bt00, bt01);
        *reinterpret_cast<float2*>(g_bt + i1) = make_float2(bt10, bt11);
        *reinterpret_cast<float2*>(&ATs[r0 * SPAD + n]) = make_float2(at00, at01);
        *reinterpret_cast<float2*>(&ATs[r1 * SPAD + n]) = make_float2(at10, at11);
        *reinterpret_cast<float2*>(&BTs[r0 * SPAD + n]) = make_float2(bt00, bt01);
        *reinterpret_cast<float2*>(&BTs[r1 * SPAD + n]) = make_float2(bt10, bt11);
    }
    __syncthreads();

    // fused chunk-state fold (was k2a): 2 dirs x 128 channels
    {
        int dir = tid >> 7, h = tid & 127;
        float Ap = 1.f, Bv = 0.f;
        if (dir == 0) {
#pragma unroll 8
            for (int s = 0; s < CS; s++) {
                float a = ATs[s * SPAD + h], bb = BTs[s * SPAD + h];
                Ap *= a;
                Bv = fmaf(a, Bv, bb);
            }
        } else {
#pragma unroll 8
            for (int s = CS - 1; s >= 0; s--) {
                float a = ATs[s * SPAD + h], bb = BTs[s * SPAD + h];
                Ap *= a;
                Bv = fmaf(a, Bv, bb);
            }
        }
        g_stA[dir][b][ci][h] = Ap;
        g_stB[dir][b][ci][h] = Bv;
    }
}

// ---------------- K34: scan + out-GEMM + LN + MLP + residual (fused) -----
__global__ __launch_bounds__(256, 2) void k34_fused(
    const float* __restrict__ x, const float* __restrict__ cvec,
    const float* __restrict__ g1w, const float* __restrict__ g1b,
    const float* __restrict__ bout,
    const float* __restrict__ sw2, const float* __restrict__ sb2,
    const float* __restrict__ bw2, const float* __restrict__ bb2,
    const float* __restrict__ g2w, const float* __restrict__ g2b,
    const float* __restrict__ b1v, const float* __restrict__ b2v,
    float* __restrict__ out)
{
    extern __shared__ float sm[];
    float* S0 = sm;                 // scan fwd -> later o (branch-1 output, fp32)
    float* S1 = sm + 64 * SPAD;     // scan bwd -> later HS (LN'd, tf32)
    float* S2 = sm + 128 * SPAD;    // M1c
    float* sS = sm + 192 * SPAD;    // 4 scalars: g1, s2, b2s, g2
    int blk = blockIdx.x;
    int b = blk >> 7, ci = blk & 127;
    int tid = threadIdx.x;
    int tbase = (b << 13) + (ci << 6);

    if (tid < 32) {
        float p0 = dot32(cvec + b * 128, g1w, tid);
        float p1 = dot32(cvec + b * 128, sw2, tid);
        float p2 = dot32(cvec + b * 128, bw2, tid);
        float p3 = dot32(cvec + b * 128, g2w, tid);
        if (tid == 0) {
            sS[0] = p0 + g1b[0];
            sS[1] = p1 + sb2[0];
            sS[2] = p2 + bb2[0];
            sS[3] = p3 + g2b[0];
        }
    }
    // ---- phase A1: chunk-prefix fold + re-scan into S0/S1 (tf32)
    {
        int dir = tid >> 7, h = tid & 127;
        float hc = 0.f;
        if (dir == 0) {
            int j = 0;
            while (j < ci) {
                int nb = ci - j; if (nb > 16) nb = 16;
                float av[16], bv[16];
#pragma unroll
                for (int q = 0; q < 16; q++)
                    if (q < nb) {
                        av[q] = g_stA[0][b][j + q][h];
                        bv[q] = g_stB[0][b][j + q][h];
                    }
#pragma unroll
                for (int q = 0; q < 16; q++)
                    if (q < nb) hc = fmaf(av[q], hc, bv[q]);
                j += nb;
            }
        } else {
            int j = NC - 1;
            while (j > ci) {
                int nb = j - ci; if (nb > 16) nb = 16;
                float av[16], bv[16];
#pragma unroll
                for (int q = 0; q < 16; q++)
                    if (q < nb) {
                        av[q] = g_stA[1][b][j - q][h];
                        bv[q] = g_stB[1][b][j - q][h];
                    }
#pragma unroll
                for (int q = 0; q < 16; q++)
                    if (q < nb) hc = fmaf(av[q], hc, bv[q]);
                j -= nb;
            }
        }
        int base = tbase * 128 + h;
        if (dir == 0) {
            for (int s0 = 0; s0 < CS; s0 += 8) {
                float av[8], bv[8];
#pragma unroll
                for (int q = 0; q < 8; q++) {
                    int idx = base + ((s0 + q) << 7);
                    av[q] = g_at[idx];
                    bv[q] = g_bt[idx];
                }
#pragma unroll
                for (int q = 0; q < 8; q++) {
                    hc = fmaf(av[q], hc, bv[q]);
                    S0[(s0 + q) * SPAD + h] = cvt_tf32(hc);
                }
            }
        } else {
            for (int s0 = CS - 1; s0 >= 0; s0 -= 8) {
                float av[8], bv[8];
#pragma unroll
                for (int q = 0; q < 8; q++) {
                    int idx = base + ((s0 - q) << 7);
                    av[q] = g_at[idx];
                    bv[q] = g_bt[idx];
                }
#pragma unroll
                for (int q = 0; q < 8; q++) {
                    hc = fmaf(av[q], hc, bv[q]);
                    S1[(s0 - q) * SPAD + h] = cvt_tf32(hc);
                }
            }
        }
    }
    __syncthreads();

    int lane = tid & 31, wid = tid >> 5;
    int g = lane >> 2, t = lane & 3;
    int wm = wid >> 1, wn = wid & 1;
    int row0 = wm * 16, col0 = wn * 64;

    // ---- phase A2: out-GEMM r = HF@WoutF + HB@WoutB
    float c[8][4];
#pragma unroll
    for (int j = 0; j < 8; j++)
#pragma unroll
        for (int e = 0; e < 4; e++) c[j][e] = 0.f;
    gemm_16x64_g(S0, g_wimg[3], row0, wn, lane, g, t, c);
    gemm_16x64_g(S1, g_wimg[4], row0, wn, lane, g, t, c);
    __syncthreads();   // all warps done reading S0/S1 before overwriting

    // ---- phase A3: o = x + g1*(c + bout) -> S0 (fp32, NOT written to gmem)
    {
        float g1 = sS[0];
#pragma unroll
        for (int j = 0; j < 8; j++) {
            int n = col0 + 8 * j + 2 * t;
            int r0 = row0 + g, r1 = r0 + 8;
            float2 bb = *reinterpret_cast<const float2*>(bout + n);
            int i0 = (tbase + r0) * 128 + n;
            int i1 = (tbase + r1) * 128 + n;
            float2 x0 = *reinterpret_cast<const float2*>(x + i0);
            float2 x1 = *reinterpret_cast<const float2*>(x + i1);
            S0[r0 * SPAD + n]     = fmaf(g1, c[j][0] + bb.x, x0.x);
            S0[r0 * SPAD + n + 1] = fmaf(g1, c[j][1] + bb.y, x0.y);
            S0[r1 * SPAD + n]     = fmaf(g1, c[j][2] + bb.x, x1.x);
            S0[r1 * SPAD + n + 1] = fmaf(g1, c[j][3] + bb.y, x1.y);
        }
    }
    __syncthreads();

    // ---- phase B1: cond-LN of o (from S0) -> HS (tf32) in S1
    {
        float alpha = 1.f + sS[1];
        float b2s = sS[2];
        int tt = tid >> 2, q = tid & 3;
        const float* op = &S0[tt * SPAD + q * 32];
        float4 v[8];
#pragma unroll
        for (int i = 0; i < 8; i++) v[i] = *reinterpret_cast<const float4*>(op + i * 4);
        float s = 0.f, ss = 0.f;
#pragma unroll
        for (int i = 0; i < 8; i++) {
            s  += v[i].x + v[i].y + v[i].z + v[i].w;
            ss += v[i].x * v[i].x + v[i].y * v[i].y + v[i].z * v[i].z + v[i].w * v[i].w;
        }
        s  += __shfl_xor_sync(0xffffffffu, s, 1);
        s  += __shfl_xor_sync(0xffffffffu, s, 2);
        ss += __shfl_xor_sync(0xffffffffu, ss, 1);
        ss += __shfl_xor_sync(0xffffffffu, ss, 2);
        float m = s * (1.f / 128.f);
        float rs = rsqrtf(ss * (1.f / 128.f) - m * m + 1e-6f);
        float* hp = &S1[tt * SPAD + q * 32];
#pragma unroll
        for (int i = 0; i < 8; i++) {
            float4 o;
            o.x = cvt_tf32(fmaf(alpha, (v[i].x - m) * rs, b2s));
            o.y = cvt_tf32(fmaf(alpha, (v[i].y - m) * rs, b2s));
            o.z = cvt_tf32(fmaf(alpha, (v[i].z - m) * rs, b2s));
            o.w = cvt_tf32(fmaf(alpha, (v[i].w - m) * rs, b2s));
            *reinterpret_cast<float4*>(hp + i * 4) = o;
        }
    }
    __syncthreads();

    // ---- phase B2: GELU MLP (4 mid-channel chunks), C2 accumulates
    float C2[8][4];
#pragma unroll
    for (int j = 0; j < 8; j++)
#pragma unroll
        for (int e = 0; e < 4; e++) C2[j][e] = 0.f;

    for (int ch = 0; ch < 4; ch++) {
        float c1[8][4];
#pragma unroll
        for (int j = 0; j < 8; j++)
#pragma unroll
            for (int e = 0; e < 4; e++) c1[j][e] = 0.f;
        gemm_16x64_g(S1, g_wimg[5 + ch], row0, wn, lane, g, t, c1);

        BARW(wm);   // prev-chunk gemm2 readers of this wm's M1c rows done
#pragma unroll
        for (int j = 0; j < 8; j++) {
            int n = col0 + 8 * j + 2 * t;
            int r0 = row0 + g, r1 = r0 + 8;
            float2 bb = *reinterpret_cast<const float2*>(b1v + ch * 128 + n);
            S2[r0 * SPAD + n]     = cvt_tf32(geluf_(c1[j][0] + bb.x));
            S2[r0 * SPAD + n + 1] = cvt_tf32(geluf_(c1[j][1] + bb.y));
            S2[r1 * SPAD + n]     = cvt_tf32(geluf_(c1[j][2] + bb.x));
            S2[r1 * SPAD + n + 1] = cvt_tf32(geluf_(c1[j][3] + bb.y));
        }
        BARW(wm);
        gemm_16x64_g(S2, g_wimg[9 + ch], row0, wn, lane, g, t, C2);
    }

    // ---- phase B3: final epilogue, single gmem out write
    {
        float g2 = sS[3];
#pragma unroll
        for (int j = 0; j < 8; j++) {
            int n = col0 + 8 * j + 2 * t;
            int r0 = row0 + g, r1 = r0 + 8;
            float2 bb = *reinterpret_cast<const float2*>(b2v + n);
            int i0 = (tbase + r0) * 128 + n;
            int i1 = (tbase + r1) * 128 + n;
            float2 o0, o1;
            o0.x = fmaf(g2, C2[j][0] + bb.x, S0[r0 * SPAD + n]);
            o0.y = fmaf(g2, C2[j][1] + bb.y, S0[r0 * SPAD + n + 1]);
            o1.x = fmaf(g2, C2[j][2] + bb.x, S0[r1 * SPAD + n]);
            o1.y = fmaf(g2, C2[j][3] + bb.y, S0[r1 * SPAD + n + 1]);
            *reinterpret_cast<float2*>(out + i0) = o0;
            *reinterpret_cast<float2*>(out + i1) = o1;
        }
    }
}

// ---------------- launch -------------------------------------------------
extern "C" void kernel_launch(void* const* d_in, const int* in_sizes, int n_in,
                              void* d_out, int out_size)
{
    const float* x        = (const float*)d_in[0];
    const float* c        = (const float*)d_in[1];
    const float* cln1_sw  = (const float*)d_in[2];
    const float* cln1_sb  = (const float*)d_in[3];
    const float* cln1_bw  = (const float*)d_in[4];
    const float* cln1_bb  = (const float*)d_in[5];
    const float* gate1_w  = (const float*)d_in[6];
    const float* gate1_b  = (const float*)d_in[7];
    const float* rnn_in_w = (const float*)d_in[8];
    const float* rnn_in_b = (const float*)d_in[9];
    const float* pos_emb  = (const float*)d_in[10];
    const float* rnn_wi   = (const float*)d_in[11];
    const float* rnn_bi   = (const float*)d_in[12];
    const float* rnn_wr   = (const float*)d_in[13];
    const float* rnn_br   = (const float*)d_in[14];
    const float* rnn_a    = (const float*)d_in[15];
    const float* rnn_out_w= (const float*)d_in[16];
    const float* rnn_out_b= (const float*)d_in[17];
    const float* cln2_sw  = (const float*)d_in[18];
    const float* cln2_sb  = (const float*)d_in[19];
    const float* cln2_bw  = (const float*)d_in[20];
    const float* cln2_bb  = (const float*)d_in[21];
    const float* gate2_w  = (const float*)d_in[22];
    const float* gate2_b  = (const float*)d_in[23];
    const float* mlp_w1   = (const float*)d_in[24];
    const float* mlp_b1   = (const float*)d_in[25];
    const float* mlp_w2   = (const float*)d_in[26];
    const float* mlp_b2   = (const float*)d_in[27];
    float* out = (float*)d_out;

    const int SM1  = (192 * SPAD + 128 + 2) * 4;      // ~102 KB -> 2 CTAs/SM
    const int SM34 = (192 * SPAD + 4) * 4;            // ~101.4 KB -> 2 CTAs/SM
    cudaFuncSetAttribute(k1_pre,    cudaFuncAttributeMaxDynamicSharedMemorySize, SM1);
    cudaFuncSetAttribute(k34_fused, cudaFuncAttributeMaxDynamicSharedMemorySize, SM34);

    kp_pack<<<13, 256>>>(rnn_in_w, rnn_wi, rnn_wr, rnn_out_w, mlp_w1, mlp_w2);
    k1_pre<<<1024, 256, SM1>>>(x, c, cln1_sw, cln1_sb, cln1_bw, cln1_bb,
                               rnn_in_b, pos_emb, rnn_bi, rnn_br, rnn_a);
    k34_fused<<<1024, 256, SM34>>>(x, c, gate1_w, gate1_b, rnn_out_b,
                                   cln2_sw, cln2_sb, cln2_bw, cln2_bb,
                                   gate2_w, gate2_b, mlp_b1, mlp_b2, out);
}

// round 15
// speedup vs baseline: 1.4245x; 1.0340x over previous
#include <cuda_runtime.h>
#include <math.h>
#include <stdint.h>

#define BSZ 8
#define SEQ 8192
#define NC  128      // chunks per sequence
#define CS  64       // chunk size == tile size
#define SPAD 132     // 132 mod 32 == 4 -> conflict-free A fragment LDS

// per-wm-pair named barrier (2 warps = 64 threads), ids 1..4
#define BARW(wmv) asm volatile("bar.sync %0, 64;" :: "r"(1 + (wmv)) : "memory")

// ---------------- scratch -----------------------------------------------
__device__ float g_at[BSZ * SEQ * 128];
__device__ float g_bt[BSZ * SEQ * 128];
__device__ float g_stA[2][BSZ][NC][128];
__device__ float g_stB[2][BSZ][NC][128];
// fragment-quad weight images: [seg][kstep(16)][ntpair(8)][lane(32)] float4
// segs: 0 Win, 1 Wi, 2 Wr, 3 WoutF, 4 WoutB, 5-8 W1 chunks, 9-12 W2 chunks
__device__ float4 g_wimg[13][4096];

__device__ __forceinline__ float sigmoidf_(float v) {
    return 1.f / (1.f + expf(-v));
}
__device__ __forceinline__ float geluf_(float v) {
    float u = v + 0.044715f * v * v * v;
    return 0.5f * v * (1.f + tanhf(0.7978845608028654f * u));
}
__device__ __forceinline__ float cvt_tf32(float x) {
    uint32_t u;
    asm("cvt.rna.tf32.f32 %0, %1;" : "=r"(u) : "f"(x));
    return __uint_as_float(u);
}
__device__ __forceinline__ void mma_tf32(float c[4],
    uint32_t a0, uint32_t a1, uint32_t a2, uint32_t a3,
    uint32_t b0, uint32_t b1)
{
    asm("mma.sync.aligned.m16n8k8.row.col.f32.tf32.tf32.f32 "
        "{%0,%1,%2,%3},{%4,%5,%6,%7},{%8,%9},{%0,%1,%2,%3};"
        : "+f"(c[0]), "+f"(c[1]), "+f"(c[2]), "+f"(c[3])
        : "r"(a0), "r"(a1), "r"(a2), "r"(a3), "r"(b0), "r"(b1));
}

// dot(c[128], w[128]) by 32 threads (tid<32); full value in lane 0.
__device__ __forceinline__ float dot32(const float* cvec, const float* w, int tid)
{
    float4 cv = reinterpret_cast<const float4*>(cvec)[tid];
    float4 wv = reinterpret_cast<const float4*>(w)[tid];
    float p = cv.x * wv.x + cv.y * wv.y + cv.z * wv.z + cv.w * wv.w;
    p += __shfl_xor_sync(0xffffffffu, p, 16);
    p += __shfl_xor_sync(0xffffffffu, p, 8);
    p += __shfl_xor_sync(0xffffffffu, p, 4);
    p += __shfl_xor_sync(0xffffffffu, p, 2);
    p += __shfl_xor_sync(0xffffffffu, p, 1);
    return p;
}

// warp computes 16(row) x 64(col) tile of A[..x128] @ W[128x..]; A in smem
// (stride SPAD); B fragment quads streamed from the gmem image with a
// 1-iteration software prefetch (LDG->use distance = one full ks step).
__device__ __forceinline__ void gemm_16x64_g(const float* __restrict__ As,
    const float4* __restrict__ Bimg, int row0, int wn, int lane, int g, int t,
    float c[8][4])
{
    const float4* B0 = Bimg + ((wn * 4) << 5) + lane;
    float4 bv0 = __ldg(B0);
    float4 bv1 = __ldg(B0 + 32);
    float4 bv2 = __ldg(B0 + 64);
    float4 bv3 = __ldg(B0 + 96);
#pragma unroll 4
    for (int ks = 0; ks < 16; ks++) {
        const float* Ar = As + (row0 + g) * SPAD + ks * 8 + t;
        uint32_t a0 = __float_as_uint(Ar[0]);
        uint32_t a2 = __float_as_uint(Ar[4]);
        uint32_t a1 = __float_as_uint(Ar[8 * SPAD]);
        uint32_t a3 = __float_as_uint(Ar[8 * SPAD + 4]);
        float4 bn0, bn1, bn2, bn3;
        if (ks < 15) {
            const float4* Bn = Bimg + (((ks + 1) * 8 + wn * 4) << 5) + lane;
            bn0 = __ldg(Bn);
            bn1 = __ldg(Bn + 32);
            bn2 = __ldg(Bn + 64);
            bn3 = __ldg(Bn + 96);
        }
        mma_tf32(c[0], a0, a1, a2, a3, __float_as_uint(bv0.x), __float_as_uint(bv0.y));
        mma_tf32(c[1], a0, a1, a2, a3, __float_as_uint(bv0.z), __float_as_uint(bv0.w));
        mma_tf32(c[2], a0, a1, a2, a3, __float_as_uint(bv1.x), __float_as_uint(bv1.y));
        mma_tf32(c[3], a0, a1, a2, a3, __float_as_uint(bv1.z), __float_as_uint(bv1.w));
        mma_tf32(c[4], a0, a1, a2, a3, __float_as_uint(bv2.x), __float_as_uint(bv2.y));
        mma_tf32(c[5], a0, a1, a2, a3, __float_as_uint(bv2.z), __float_as_uint(bv2.w));
        mma_tf32(c[6], a0, a1, a2, a3, __float_as_uint(bv3.x), __float_as_uint(bv3.y));
        mma_tf32(c[7], a0, a1, a2, a3, __float_as_uint(bv3.z), __float_as_uint(bv3.w));
        bv0 = bn0; bv1 = bn1; bv2 = bn2; bv3 = bn3;
    }
}

// ---------------- KP: pack all weights into fragment-quad images ---------
// 8 blocks per segment (104 blocks total); each block packs 512 entries.
__global__ __launch_bounds__(256) void kp_pack(
    const float* __restrict__ Win, const float* __restrict__ Wi,
    const float* __restrict__ Wr,  const float* __restrict__ Wout,
    const float* __restrict__ W1,  const float* __restrict__ W2)
{
    int seg = blockIdx.x >> 3;
    int part = blockIdx.x & 7;
    const float* src;
    int ns;
    if (seg == 0)      { src = Win;  ns = 128; }
    else if (seg == 1) { src = Wi;   ns = 128; }
    else if (seg == 2) { src = Wr;   ns = 128; }
    else if (seg == 3) { src = Wout; ns = 128; }
    else if (seg == 4) { src = Wout + 128 * 128; ns = 128; }
    else if (seg < 9)  { src = W1 + (seg - 5) * 128; ns = 512; }
    else               { src = W2 + (seg - 9) * 128 * 128; ns = 128; }
    float4* dst = g_wimg[seg];
    int p0 = part * 512;
#pragma unroll
    for (int it = 0; it < 2; it++) {
        int p = p0 + it * 256 + threadIdx.x;
        int lane = p & 31, ntp = (p >> 5) & 7, ks = p >> 8;
        int g = lane >> 2, t = lane & 3;
        int k = ks * 8 + t, n = ntp * 16 + g;
        dst[p] = make_float4(cvt_tf32(src[k * ns + n]),
                             cvt_tf32(src[(k + 4) * ns + n]),
                             cvt_tf32(src[k * ns + n + 8]),
                             cvt_tf32(src[(k + 4) * ns + n + 8]));
    }
}

// ---------------- K1: LN->LN->(u,gates)->a_t,b_t + chunk states ----------
__global__ __launch_bounds__(256, 2) void k1_pre(
    const float* __restrict__ x,   const float* __restrict__ cvec,
    const float* __restrict__ sw1, const float* __restrict__ sb1,
    const float* __restrict__ bw1, const float* __restrict__ bb1,
    const float* __restrict__ bin, const float* __restrict__ pos,
    const float* __restrict__ bi,  const float* __restrict__ br,
    const float* __restrict__ avec)
{
    extern __shared__ float sm[];
    float* As  = sm;                          // 64*SPAD
    float* ATs = sm + 64 * SPAD;              // 64*SPAD (a_t tile)
    float* BTs = sm + 128 * SPAD;             // 64*SPAD (b_t tile)
    float* L2A = sm + 192 * SPAD;             // 128
    float* sS  = L2A + 128;                   // 2
    int tid = threadIdx.x;
    int blk = blockIdx.x;
    int to  = blk * 64;
    int b   = blk >> 7;
    int ci  = blk & 127;
    int tib = to & (SEQ - 1);

    if (tid < 32) {
        float p0 = dot32(cvec + b * 128, sw1, tid);
        float p1 = dot32(cvec + b * 128, bw1, tid);
        if (tid == 0) { sS[0] = p0 + sb1[0]; sS[1] = p1 + bb1[0]; }
    }
    if (tid >= 128) L2A[tid - 128] = log2f(avec[tid - 128]);
    __syncthreads();
    float alpha = 1.f + sS[0];
    float b1s   = sS[1];

    // ---- LN x2 : 4 threads per token, 32 channels each
    {
        int tt = tid >> 2, q = tid & 3;
        const float4* xp = reinterpret_cast<const float4*>(x + (to + tt) * 128 + q * 32);
        float4 v[8];
#pragma unroll
        for (int i = 0; i < 8; i++) v[i] = xp[i];
        float s = 0.f, ss = 0.f;
#pragma unroll
        for (int i = 0; i < 8; i++) {
            s  += v[i].x + v[i].y + v[i].z + v[i].w;
            ss += v[i].x * v[i].x + v[i].y * v[i].y + v[i].z * v[i].z + v[i].w * v[i].w;
        }
        s  += __shfl_xor_sync(0xffffffffu, s, 1);
        s  += __shfl_xor_sync(0xffffffffu, s, 2);
        ss += __shfl_xor_sync(0xffffffffu, ss, 1);
        ss += __shfl_xor_sync(0xffffffffu, ss, 2);
        float m = s * (1.f / 128.f);
        float rs = rsqrtf(ss * (1.f / 128.f) - m * m + 1e-6f);
        float s2 = 0.f, ss2 = 0.f;
#pragma unroll
        for (int i = 0; i < 8; i++) {
            v[i].x = fmaf(alpha, (v[i].x - m) * rs, b1s);
            v[i].y = fmaf(alpha, (v[i].y - m) * rs, b1s);
            v[i].z = fmaf(alpha, (v[i].z - m) * rs, b1s);
            v[i].w = fmaf(alpha, (v[i].w - m) * rs, b1s);
            s2  += v[i].x + v[i].y + v[i].z + v[i].w;
            ss2 += v[i].x * v[i].x + v[i].y * v[i].y + v[i].z * v[i].z + v[i].w * v[i].w;
        }
        s2  += __shfl_xor_sync(0xffffffffu, s2, 1);
        s2  += __shfl_xor_sync(0xffffffffu, s2, 2);
        ss2 += __shfl_xor_sync(0xffffffffu, ss2, 1);
        ss2 += __shfl_xor_sync(0xffffffffu, ss2, 2);
        float m2 = s2 * (1.f / 128.f);
        float rs2 = rsqrtf(ss2 * (1.f / 128.f) - m2 * m2 + 1e-6f);
        float* Ap = &As[tt * SPAD + q * 32];
#pragma unroll
        for (int i = 0; i < 8; i++) {
            float4 o;
            o.x = cvt_tf32((v[i].x - m2) * rs2);
            o.y = cvt_tf32((v[i].y - m2) * rs2);
            o.z = cvt_tf32((v[i].z - m2) * rs2);
            o.w = cvt_tf32((v[i].w - m2) * rs2);
            *reinterpret_cast<float4*>(Ap + i * 4) = o;
        }
    }
    __syncthreads();

    int lane = tid & 31, wid = tid >> 5;
    int g = lane >> 2, t = lane & 3;
    int wm = wid >> 1, wn = wid & 1;
    int row0 = wm * 16, col0 = wn * 64;

    // GEMM1: u = ln2h @ Win
    float c1[8][4];
#pragma unroll
    for (int j = 0; j < 8; j++)
#pragma unroll
        for (int e = 0; e < 4; e++) c1[j][e] = 0.f;
    gemm_16x64_g(As, g_wimg[0], row0, wn, lane, g, t, c1);
    BARW(wm);   // As rows [row0,row0+16) touched only by this wm pair

    // u = c1 + bin + pos -> back into As (tf32)
#pragma unroll
    for (int j = 0; j < 8; j++) {
        int n = col0 + 8 * j + 2 * t;
        int r0 = row0 + g, r1 = r0 + 8;
        float2 bb = *reinterpret_cast<const float2*>(bin + n);
        float2 p0 = *reinterpret_cast<const float2*>(pos + (tib + r0) * 128 + n);
        float2 p1 = *reinterpret_cast<const float2*>(pos + (tib + r1) * 128 + n);
        As[r0 * SPAD + n]     = cvt_tf32(c1[j][0] + bb.x + p0.x);
        As[r0 * SPAD + n + 1] = cvt_tf32(c1[j][1] + bb.y + p0.y);
        As[r1 * SPAD + n]     = cvt_tf32(c1[j][2] + bb.x + p1.x);
        As[r1 * SPAD + n + 1] = cvt_tf32(c1[j][3] + bb.y + p1.y);
    }
    BARW(wm);

    // GEMM2: input gate
    float gi[8][4];
#pragma unroll
    for (int j = 0; j < 8; j++)
#pragma unroll
        for (int e = 0; e < 4; e++) gi[j][e] = 0.f;
    gemm_16x64_g(As, g_wimg[1], row0, wn, lane, g, t, gi);
#pragma unroll
    for (int j = 0; j < 8; j++) {
        int n = col0 + 8 * j + 2 * t;
        float2 bb = *reinterpret_cast<const float2*>(bi + n);
        gi[j][0] = sigmoidf_(gi[j][0] + bb.x);
        gi[j][1] = sigmoidf_(gi[j][1] + bb.y);
        gi[j][2] = sigmoidf_(gi[j][2] + bb.x);
        gi[j][3] = sigmoidf_(gi[j][3] + bb.y);
    }

    // GEMM3: recurrence gate (As unchanged, no sync needed)
#pragma unroll
    for (int j = 0; j < 8; j++)
#pragma unroll
        for (int e = 0; e < 4; e++) c1[j][e] = 0.f;
    gemm_16x64_g(As, g_wimg[2], row0, wn, lane, g, t, c1);

    // epilogue: a_t, b_t -> gmem AND smem tiles
#pragma unroll
    for (int j = 0; j < 8; j++) {
        int n = col0 + 8 * j + 2 * t;
        int r0 = row0 + g, r1 = r0 + 8;
        float2 bb = *reinterpret_cast<const float2*>(br + n);
        float la0 = L2A[n], la1 = L2A[n + 1];
        float u00 = As[r0 * SPAD + n], u01 = As[r0 * SPAD + n + 1];
        float u10 = As[r1 * SPAD + n], u11 = As[r1 * SPAD + n + 1];
        float at00 = exp2f(8.f * sigmoidf_(c1[j][0] + bb.x) * la0);
        float at01 = exp2f(8.f * sigmoidf_(c1[j][1] + bb.y) * la1);
        float at10 = exp2f(8.f * sigmoidf_(c1[j][2] + bb.x) * la0);
        float at11 = exp2f(8.f * sigmoidf_(c1[j][3] + bb.y) * la1);
        float bt00 = sqrtf(fmaxf(1.f - at00 * at00, 0.f)) * gi[j][0] * u00;
        float bt01 = sqrtf(fmaxf(1.f - at01 * at01, 0.f)) * gi[j][1] * u01;
        float bt10 = sqrtf(fmaxf(1.f - at10 * at10, 0.f)) * gi[j][2] * u10;
        float bt11 = sqrtf(fmaxf(1.f - at11 * at11, 0.f)) * gi[j][3] * u11;
        int i0 = (to + r0) * 128 + n;
        int i1 = (to + r1) * 128 + n;
        *reinterpret_cast<float2*>(g_at + i0) = make_float2(at00, at01);
        *reinterpret_cast<float2*>(g_at + i1) = make_float2(at10, at11);
        *reinterpret_cast<float2*>(g_bt + i0) = make_float2(bt00, bt01);
        *reinterpret_cast<float2*>(g_bt + i1) = make_float2(bt10, bt11);
        *reinterpret_cast<float2*>(&ATs[r0 * SPAD + n]) = make_float2(at00, at01);
        *reinterpret_cast<float2*>(&ATs[r1 * SPAD + n]) = make_float2(at10, at11);
        *reinterpret_cast<float2*>(&BTs[r0 * SPAD + n]) = make_float2(bt00, bt01);
        *reinterpret_cast<float2*>(&BTs[r1 * SPAD + n]) = make_float2(bt10, bt11);
    }
    __syncthreads();

    // fused chunk-state fold (was k2a): 2 dirs x 128 channels
    {
        int dir = tid >> 7, h = tid & 127;
        float Ap = 1.f, Bv = 0.f;
        if (dir == 0) {
#pragma unroll 8
            for (int s = 0; s < CS; s++) {
                float a = ATs[s * SPAD + h], bb = BTs[s * SPAD + h];
                Ap *= a;
                Bv = fmaf(a, Bv, bb);
            }
        } else {
#pragma unroll 8
            for (int s = CS - 1; s >= 0; s--) {
                float a = ATs[s * SPAD + h], bb = BTs[s * SPAD + h];
                Ap *= a;
                Bv = fmaf(a, Bv, bb);
            }
        }
        g_stA[dir][b][ci][h] = Ap;
        g_stB[dir][b][ci][h] = Bv;
    }
}

// ---------------- K34: scan + out-GEMM + LN + MLP + residual (fused) -----
__global__ __launch_bounds__(256, 2) void k34_fused(
    const float* __restrict__ x, const float* __restrict__ cvec,
    const float* __restrict__ g1w, const float* __restrict__ g1b,
    const float* __restrict__ bout,
    const float* __restrict__ sw2, const float* __restrict__ sb2,
    const float* __restrict__ bw2, const float* __restrict__ bb2,
    const float* __restrict__ g2w, const float* __restrict__ g2b,
    const float* __restrict__ b1v, const float* __restrict__ b2v,
    float* __restrict__ out)
{
    extern __shared__ float sm[];
    float* S0 = sm;                 // scan fwd -> later o (branch-1 output, fp32)
    float* S1 = sm + 64 * SPAD;     // scan bwd -> later HS (LN'd, tf32)
    float* S2 = sm + 128 * SPAD;    // M1c
    float* sS = sm + 192 * SPAD;    // 4 scalars: g1, s2, b2s, g2
    int blk = blockIdx.x;
    int b = blk >> 7, ci = blk & 127;
    int tid = threadIdx.x;
    int tbase = (b << 13) + (ci << 6);

    if (tid < 32) {
        float p0 = dot32(cvec + b * 128, g1w, tid);
        float p1 = dot32(cvec + b * 128, sw2, tid);
        float p2 = dot32(cvec + b * 128, bw2, tid);
        float p3 = dot32(cvec + b * 128, g2w, tid);
        if (tid == 0) {
            sS[0] = p0 + g1b[0];
            sS[1] = p1 + sb2[0];
            sS[2] = p2 + bb2[0];
            sS[3] = p3 + g2b[0];
        }
    }
    // ---- phase A1: chunk-prefix fold + re-scan into S0/S1 (tf32)
    {
        int dir = tid >> 7, h = tid & 127;
        float hc = 0.f;
        if (dir == 0) {
            int j = 0;
            while (j < ci) {
                int nb = ci - j; if (nb > 16) nb = 16;
                float av[16], bv[16];
#pragma unroll
                for (int q = 0; q < 16; q++)
                    if (q < nb) {
                        av[q] = g_stA[0][b][j + q][h];
                        bv[q] = g_stB[0][b][j + q][h];
                    }
#pragma unroll
                for (int q = 0; q < 16; q++)
                    if (q < nb) hc = fmaf(av[q], hc, bv[q]);
                j += nb;
            }
        } else {
            int j = NC - 1;
            while (j > ci) {
                int nb = j - ci; if (nb > 16) nb = 16;
                float av[16], bv[16];
#pragma unroll
                for (int q = 0; q < 16; q++)
                    if (q < nb) {
                        av[q] = g_stA[1][b][j - q][h];
                        bv[q] = g_stB[1][b][j - q][h];
                    }
#pragma unroll
                for (int q = 0; q < 16; q++)
                    if (q < nb) hc = fmaf(av[q], hc, bv[q]);
                j -= nb;
            }
        }
        int base = tbase * 128 + h;
        if (dir == 0) {
            for (int s0 = 0; s0 < CS; s0 += 8) {
                float av[8], bv[8];
#pragma unroll
                for (int q = 0; q < 8; q++) {
                    int idx = base + ((s0 + q) << 7);
                    av[q] = g_at[idx];
                    bv[q] = g_bt[idx];
                }
#pragma unroll
                for (int q = 0; q < 8; q++) {
                    hc = fmaf(av[q], hc, bv[q]);
                    S0[(s0 + q) * SPAD + h] = cvt_tf32(hc);
                }
            }
        } else {
            for (int s0 = CS - 1; s0 >= 0; s0 -= 8) {
                float av[8], bv[8];
#pragma unroll
                for (int q = 0; q < 8; q++) {
                    int idx = base + ((s0 - q) << 7);
                    av[q] = g_at[idx];
                    bv[q] = g_bt[idx];
                }
#pragma unroll
                for (int q = 0; q < 8; q++) {
                    hc = fmaf(av[q], hc, bv[q]);
                    S1[(s0 - q) * SPAD + h] = cvt_tf32(hc);
                }
            }
        }
    }
    __syncthreads();

    int lane = tid & 31, wid = tid >> 5;
    int g = lane >> 2, t = lane & 3;
    int wm = wid >> 1, wn = wid & 1;
    int row0 = wm * 16, col0 = wn * 64;

    // ---- phase A2: out-GEMM r = HF@WoutF + HB@WoutB
    float c[8][4];
#pragma unroll
    for (int j = 0; j < 8; j++)
#pragma unroll
        for (int e = 0; e < 4; e++) c[j][e] = 0.f;
    gemm_16x64_g(S0, g_wimg[3], row0, wn, lane, g, t, c);
    gemm_16x64_g(S1, g_wimg[4], row0, wn, lane, g, t, c);
    __syncthreads();   // all warps done reading S0/S1 before overwriting

    // ---- phase A3: o = x + g1*(c + bout) -> S0 (fp32, NOT written to gmem)
    {
        float g1 = sS[0];
#pragma unroll
        for (int j = 0; j < 8; j++) {
            int n = col0 + 8 * j + 2 * t;
            int r0 = row0 + g, r1 = r0 + 8;
            float2 bb = *reinterpret_cast<const float2*>(bout + n);
            int i0 = (tbase + r0) * 128 + n;
            int i1 = (tbase + r1) * 128 + n;
            float2 x0 = *reinterpret_cast<const float2*>(x + i0);
            float2 x1 = *reinterpret_cast<const float2*>(x + i1);
            S0[r0 * SPAD + n]     = fmaf(g1, c[j][0] + bb.x, x0.x);
            S0[r0 * SPAD + n + 1] = fmaf(g1, c[j][1] + bb.y, x0.y);
            S0[r1 * SPAD + n]     = fmaf(g1, c[j][2] + bb.x, x1.x);
            S0[r1 * SPAD + n + 1] = fmaf(g1, c[j][3] + bb.y, x1.y);
        }
    }
    __syncthreads();

    // ---- phase B1: cond-LN of o (from S0) -> HS (tf32) in S1
    {
        float alpha = 1.f + sS[1];
        float b2s = sS[2];
        int tt = tid >> 2, q = tid & 3;
        const float* op = &S0[tt * SPAD + q * 32];
        float4 v[8];
#pragma unroll
        for (int i = 0; i < 8; i++) v[i] = *reinterpret_cast<const float4*>(op + i * 4);
        float s = 0.f, ss = 0.f;
#pragma unroll
        for (int i = 0; i < 8; i++) {
            s  += v[i].x + v[i].y + v[i].z + v[i].w;
            ss += v[i].x * v[i].x + v[i].y * v[i].y + v[i].z * v[i].z + v[i].w * v[i].w;
        }
        s  += __shfl_xor_sync(0xffffffffu, s, 1);
        s  += __shfl_xor_sync(0xffffffffu, s, 2);
        ss += __shfl_xor_sync(0xffffffffu, ss, 1);
        ss += __shfl_xor_sync(0xffffffffu, ss, 2);
        float m = s * (1.f / 128.f);
        float rs = rsqrtf(ss * (1.f / 128.f) - m * m + 1e-6f);
        float* hp = &S1[tt * SPAD + q * 32];
#pragma unroll
        for (int i = 0; i < 8; i++) {
            float4 o;
            o.x = cvt_tf32(fmaf(alpha, (v[i].x - m) * rs, b2s));
            o.y = cvt_tf32(fmaf(alpha, (v[i].y - m) * rs, b2s));
            o.z = cvt_tf32(fmaf(alpha, (v[i].z - m) * rs, b2s));
            o.w = cvt_tf32(fmaf(alpha, (v[i].w - m) * rs, b2s));
            *reinterpret_cast<float4*>(hp + i * 4) = o;
        }
    }
    __syncthreads();

    // ---- phase B2: GELU MLP (4 mid-channel chunks), C2 accumulates
    float C2[8][4];
#pragma unroll
    for (int j = 0; j < 8; j++)
#pragma unroll
        for (int e = 0; e < 4; e++) C2[j][e] = 0.f;

    for (int ch = 0; ch < 4; ch++) {
        float c1[8][4];
#pragma unroll
        for (int j = 0; j < 8; j++)
#pragma unroll
            for (int e = 0; e < 4; e++) c1[j][e] = 0.f;
        gemm_16x64_g(S1, g_wimg[5 + ch], row0, wn, lane, g, t, c1);

        BARW(wm);   // prev-chunk gemm2 readers of this wm's M1c rows done
#pragma unroll
        for (int j = 0; j < 8; j++) {
            int n = col0 + 8 * j + 2 * t;
            int r0 = row0 + g, r1 = r0 + 8;
            float2 bb = *reinterpret_cast<const float2*>(b1v + ch * 128 + n);
            S2[r0 * SPAD + n]     = cvt_tf32(geluf_(c1[j][0] + bb.x));
            S2[r0 * SPAD + n + 1] = cvt_tf32(geluf_(c1[j][1] + bb.y));
            S2[r1 * SPAD + n]     = cvt_tf32(geluf_(c1[j][2] + bb.x));
            S2[r1 * SPAD + n + 1] = cvt_tf32(geluf_(c1[j][3] + bb.y));
        }
        BARW(wm);
        gemm_16x64_g(S2, g_wimg[9 + ch], row0, wn, lane, g, t, C2);
    }

    // ---- phase B3: final epilogue, single gmem out write
    {
        float g2 = sS[3];
#pragma unroll
        for (int j = 0; j < 8; j++) {
            int n = col0 + 8 * j + 2 * t;
            int r0 = row0 + g, r1 = r0 + 8;
            float2 bb = *reinterpret_cast<const float2*>(b2v + n);
            int i0 = (tbase + r0) * 128 + n;
            int i1 = (tbase + r1) * 128 + n;
            float2 o0, o1;
            o0.x = fmaf(g2, C2[j][0] + bb.x, S0[r0 * SPAD + n]);
            o0.y = fmaf(g2, C2[j][1] + bb.y, S0[r0 * SPAD + n + 1]);
            o1.x = fmaf(g2, C2[j][2] + bb.x, S0[r1 * SPAD + n]);
            o1.y = fmaf(g2, C2[j][3] + bb.y, S0[r1 * SPAD + n + 1]);
            *reinterpret_cast<float2*>(out + i0) = o0;
            *reinterpret_cast<float2*>(out + i1) = o1;
        }
    }
}

// ---------------- launch -------------------------------------------------
extern "C" void kernel_launch(void* const* d_in, const int* in_sizes, int n_in,
                              void* d_out, int out_size)
{
    const float* x        = (const float*)d_in[0];
    const float* c        = (const float*)d_in[1];
    const float* cln1_sw  = (const float*)d_in[2];
    const float* cln1_sb  = (const float*)d_in[3];
    const float* cln1_bw  = (const float*)d_in[4];
    const float* cln1_bb  = (const float*)d_in[5];
    const float* gate1_w  = (const float*)d_in[6];
    const float* gate1_b  = (const float*)d_in[7];
    const float* rnn_in_w = (const float*)d_in[8];
    const float* rnn_in_b = (const float*)d_in[9];
    const float* pos_emb  = (const float*)d_in[10];
    const float* rnn_wi   = (const float*)d_in[11];
    const float* rnn_bi   = (const float*)d_in[12];
    const float* rnn_wr   = (const float*)d_in[13];
    const float* rnn_br   = (const float*)d_in[14];
    const float* rnn_a    = (const float*)d_in[15];
    const float* rnn_out_w= (const float*)d_in[16];
    const float* rnn_out_b= (const float*)d_in[17];
    const float* cln2_sw  = (const float*)d_in[18];
    const float* cln2_sb  = (const float*)d_in[19];
    const float* cln2_bw  = (const float*)d_in[20];
    const float* cln2_bb  = (const float*)d_in[21];
    const float* gate2_w  = (const float*)d_in[22];
    const float* gate2_b  = (const float*)d_in[23];
    const float* mlp_w1   = (const float*)d_in[24];
    const float* mlp_b1   = (const float*)d_in[25];
    const float* mlp_w2   = (const float*)d_in[26];
    const float* mlp_b2   = (const float*)d_in[27];
    float* out = (float*)d_out;

    const int SM1  = (192 * SPAD + 128 + 2) * 4;      // ~102 KB -> 2 CTAs/SM
    const int SM34 = (192 * SPAD + 4) * 4;            // ~101.4 KB -> 2 CTAs/SM
    cudaFuncSetAttribute(k1_pre,    cudaFuncAttributeMaxDynamicSharedMemorySize, SM1);
    cudaFuncSetAttribute(k34_fused, cudaFuncAttributeMaxDynamicSharedMemorySize, SM34);

    kp_pack<<<104, 256>>>(rnn_in_w, rnn_wi, rnn_wr, rnn_out_w, mlp_w1, mlp_w2);
    k1_pre<<<1024, 256, SM1>>>(x, c, cln1_sw, cln1_sb, cln1_bw, cln1_bb,
                               rnn_in_b, pos_emb, rnn_bi, rnn_br, rnn_a);
    k34_fused<<<1024, 256, SM34>>>(x, c, gate1_w, gate1_b, rnn_out_b,
                                   cln2_sw, cln2_sb, cln2_bw, cln2_bb,
                                   gate2_w, gate2_b, mlp_b1, mlp_b2, out);
}